// round 9
// baseline (speedup 1.0000x reference)
#include <cuda_runtime.h>
#include <cuda_bf16.h>
#include <cstdint>
#include <math.h>

// ===========================================================================
// TaskGraphGAT — round 6: HMMA bf16 3-product, warp-local attention.
// Change vs R5: non-volatile MMA asm + jp-pair 3-pass MMA ordering to break
// accumulator RAW chains (tensor pipe was 46% busy, issue 31%).
// ===========================================================================

#define PB   272        // bf16 tile pitch in BYTES (136 bf16), LDSM conflict-free

// ---------------- SMEM map (bytes) ----------------
#define SM_HHI   0          // h hi (128 x 136 bf16 = 34816 B)
#define SM_HLO   34816
#define SM_PHI   69632      // W hi/lo (GEMM1 B)
#define SM_PLO   104448
#define SM_S     139264     // outW hi/lo (GEMM2 B)
#define SM_SLO   174080
#define SM_SMALL 208896     // sa[2][256] | lnb[2][384] | ewf[64] | adji[64]
#define SMEM_BYTES 214528

// ---------------- device globals (written by prep) ----------------
__device__ float g_htask[8 * 128];
__device__ __align__(16) __nv_bfloat16 g_Whi[8 * 16384];
__device__ __align__(16) __nv_bfloat16 g_Wlo[8 * 16384];
__device__ __align__(16) __nv_bfloat16 g_OWhi[8 * 16384];
__device__ __align__(16) __nv_bfloat16 g_OWlo[8 * 16384];

// ---------------- helpers ----------------
__device__ __forceinline__ uint32_t smem_u32(const void* p) {
    uint32_t a;
    asm("{ .reg .u64 t; cvta.to.shared.u64 t, %1; cvt.u32.u64 %0, t; }" : "=r"(a) : "l"(p));
    return a;
}
__device__ __forceinline__ void ldsm4(uint32_t* r, uint32_t a) {
    asm volatile("ldmatrix.sync.aligned.m8n8.x4.shared.b16 {%0,%1,%2,%3}, [%4];"
                 : "=r"(r[0]), "=r"(r[1]), "=r"(r[2]), "=r"(r[3]) : "r"(a));
}
// NOTE: non-volatile on purpose — register-only op; lets ptxas interleave
// MMAs across independent accumulators to hide HMMA latency.
__device__ __forceinline__ void mma16816(float* c, const uint32_t* a, const uint32_t* b) {
    asm("mma.sync.aligned.m16n8k16.row.col.f32.bf16.bf16.f32 "
        "{%0,%1,%2,%3}, {%4,%5,%6,%7}, {%8,%9}, {%0,%1,%2,%3};"
        : "+f"(c[0]), "+f"(c[1]), "+f"(c[2]), "+f"(c[3])
        : "r"(a[0]), "r"(a[1]), "r"(a[2]), "r"(a[3]), "r"(b[0]), "r"(b[1]));
}
__device__ __forceinline__ void cpa16(uint32_t dst, const void* src) {
    asm volatile("cp.async.cg.shared.global [%0], [%1], 16;" :: "r"(dst), "l"(src));
}
#define CP_COMMIT() asm volatile("cp.async.commit_group;" ::: "memory")
#define CP_WAIT0()  asm volatile("cp.async.wait_group 0;" ::: "memory")

__device__ __forceinline__ uint32_t pack2(float x0, float x1) {
    __nv_bfloat162 v = __floats2bfloat162_rn(x0, x1);
    return *(uint32_t*)&v;
}
__device__ __forceinline__ uint32_t pack2lo(float x0, float h0, float x1, float h1) {
    __nv_bfloat162 v = __floats2bfloat162_rn(x0 - h0, x1 - h1);
    return *(uint32_t*)&v;
}
__device__ __forceinline__ float bfu(uint32_t u) {
    return __bfloat162float(__ushort_as_bfloat16((unsigned short)(u & 0xffff)));
}

// stage a hi/lo bf16 128x128 tile pair into pitched SMEM via cp.async
__device__ __forceinline__ void stage_pair(uint32_t dhi, uint32_t dlo,
                                           const uint4* shi, const uint4* slo, int tid) {
#pragma unroll
    for (int i = tid; i < 2048; i += 256) {
        uint32_t d = ((uint32_t)(i >> 4) * PB) + ((i & 15) << 4);
        cpa16(dhi + d, shi + i);
        cpa16(dlo + d, slo + i);
    }
}

// 12 MMAs over 4 accumulators (jp-pair, 3-pass ordering; reuse distance 4)
__device__ __forceinline__ void mma_block(float (&c)[16][4], int q0,
                                          const uint32_t* ah, const uint32_t* al,
                                          const uint32_t* bh0, const uint32_t* bl0,
                                          const uint32_t* bh1, const uint32_t* bl1) {
    mma16816(c[q0 + 0], ah, bh0);
    mma16816(c[q0 + 1], ah, bh0 + 2);
    mma16816(c[q0 + 2], ah, bh1);
    mma16816(c[q0 + 3], ah, bh1 + 2);
    mma16816(c[q0 + 0], ah, bl0);
    mma16816(c[q0 + 1], ah, bl0 + 2);
    mma16816(c[q0 + 2], ah, bl1);
    mma16816(c[q0 + 3], ah, bl1 + 2);
    mma16816(c[q0 + 0], al, bh0);
    mma16816(c[q0 + 1], al, bh0 + 2);
    mma16816(c[q0 + 2], al, bh1);
    mma16816(c[q0 + 3], al, bh1 + 2);
}

// GEMM1: c[q][0..3] += A(hi/lo)[rows R..R+15] @ B(hi/lo)^T, cols q*8+tg*2(+1)
__device__ __forceinline__ void gemm1(uint32_t aHi, uint32_t aLo,
                                      uint32_t bHi, uint32_t bLo,
                                      float (&c)[16][4], int R, int lid) {
    const int lm = lid >> 3, lr = lid & 7;
    const uint32_t aoff = (uint32_t)(R + lr + ((lm & 1) << 3)) * PB + ((lm >> 1) << 4);
    const uint32_t boff = (uint32_t)(lr + ((lm >> 1) << 3)) * PB + ((lm & 1) << 4);
#pragma unroll 2
    for (int k = 0; k < 8; k++) {
        uint32_t ah[4], al[4];
        ldsm4(ah, aHi + aoff + k * 32);
        ldsm4(al, aLo + aoff + k * 32);
#pragma unroll
        for (int jp2 = 0; jp2 < 4; jp2++) {
            uint32_t bh0[4], bl0[4], bh1[4], bl1[4];
            uint32_t bo0 = boff + (uint32_t)(jp2 * 32) * PB + k * 32;
            uint32_t bo1 = bo0 + (uint32_t)16 * PB;
            ldsm4(bh0, bHi + bo0);
            ldsm4(bl0, bLo + bo0);
            ldsm4(bh1, bHi + bo1);
            ldsm4(bl1, bLo + bo1);
            mma_block(c, jp2 * 4, ah, al, bh0, bl0, bh1, bl1);
        }
    }
}

// ---------------- single setup kernel ----------------
__global__ void prep(const float* __restrict__ te, const float* __restrict__ W_in,
                     const float* __restrict__ b_in, const float* __restrict__ Wh,
                     const float* __restrict__ OW, const float* __restrict__ om_i,
                     const float* __restrict__ om_c, const int* __restrict__ adj,
                     const int* __restrict__ et, float* __restrict__ out_tail) {
    int idx = blockIdx.x * 256 + threadIdx.x;   // grid 512 -> 131072 = 8*16384
    {
        int t = idx >> 14, rem = idx & 16383, row = rem >> 7, col = rem & 127;
        float w = Wh[idx];                       // W_heads[t][g=row][f=col]
        __nv_bfloat16 h = __float2bfloat16(w);
        g_Whi[idx] = h;
        g_Wlo[idx] = __float2bfloat16(w - __bfloat162float(h));
        int l = t >> 2, hh = t & 3;              // out_W[l][c=row][hh*128+g=col]
        float w2 = OW[l * 65536 + row * 512 + hh * 128 + col];
        __nv_bfloat16 h2 = __float2bfloat16(w2);
        g_OWhi[idx] = h2;
        g_OWlo[idx] = __float2bfloat16(w2 - __bfloat162float(h2));
    }
    if (blockIdx.x == 0) {
        int t = threadIdx.x;
        if (t < 64) {
            float w = 0.f;
            if (adj[t]) { int e = et[t]; w = (e == 1) ? om_i[0] : ((e == 2) ? om_c[0] : 1.f); }
            out_tail[t] = w;
        }
        for (int i2 = t; i2 < 1024; i2 += 256) {
            int n = i2 >> 7, o = i2 & 127;
            const float* tr = te + n * 64;
            const float* wr = W_in + o * 64;
            float s = b_in[o];
#pragma unroll 8
            for (int d = 0; d < 64; d++) s += tr[d] * wr[d];
            g_htask[i2] = s;
        }
    }
}

// ---------------- main kernel ----------------
__global__ __launch_bounds__(256, 1)
void gat_tc(const float* __restrict__ se, const float* __restrict__ a_heads,
            const float* __restrict__ out_b, const float* __restrict__ ln_s,
            const float* __restrict__ ln_b, const int* __restrict__ adj,
            const int* __restrict__ et, const float* __restrict__ om_i,
            const float* __restrict__ om_c, float* __restrict__ out)
{
    extern __shared__ __align__(1024) unsigned char sm[];
    float* smf  = (float*)(sm + SM_SMALL);
    float* sa   = smf;                // [2][256]
    float* lnb  = smf + 512;          // [2][384]: out_b | ln_scale | ln_bias
    float* ewf  = smf + 1280;         // [64]
    int*   adji = (int*)(smf + 1344); // [64]

    const uint32_t smb = smem_u32(sm);
    const int tid = threadIdx.x;
    const int lid = tid & 31;
    const int wid = tid >> 5;
    const int R     = wid << 4;
    const int group = lid >> 2;
    const int tg    = lid & 3;
    const long b0 = (long)blockIdx.x * 16;

    // ---- prefetch head-0 weights ASAP ----
    stage_pair(smb + SM_PHI, smb + SM_PLO, (const uint4*)g_Whi,  (const uint4*)g_Wlo,  tid);
    stage_pair(smb + SM_S,   smb + SM_SLO, (const uint4*)g_OWhi, (const uint4*)g_OWlo, tid);
    CP_COMMIT();

    // ---- small constants ----
    if (tid < 64) {
        int e = et[tid];
        ewf[tid] = adj[tid] ? ((e == 1) ? om_i[0] : ((e == 2) ? om_c[0] : 1.f)) : 0.f;
        adji[tid] = adj[tid];
    }
    sa[tid] = a_heads[tid];
    if (tid < 128) {
#pragma unroll
        for (int l = 0; l < 2; l++) {
            lnb[l * 384 + tid]       = out_b[l * 128 + tid];
            lnb[l * 384 + 128 + tid] = ln_s[l * 128 + tid];
            lnb[l * 384 + 256 + tid] = ln_b[l * 128 + tid];
        }
    }

    // ---- build h tiles (hi/lo bf16): row r = bb*8+nn ----
    {
        int r = tid & 127, f0 = (tid >> 7) * 64;
        const float* ser = se + (b0 + (r >> 3)) * 128;
        const float* htr = g_htask + (r & 7) * 128;
#pragma unroll 8
        for (int j = 0; j < 64; j += 2) {
            int f = f0 + j;
            float x0 = ser[f] + htr[f];
            float x1 = ser[f + 1] + htr[f + 1];
            uint32_t hiw = pack2(x0, x1);
            *(uint32_t*)(sm + SM_HHI + r * PB + f * 2) = hiw;
            *(uint32_t*)(sm + SM_HLO + r * PB + f * 2) =
                pack2lo(x0, bfu(hiw), x1, bfu(hiw >> 16));
        }
    }
    CP_WAIT0();
    __syncthreads();

    for (int l = 0; l < 2; l++) {
        float gacc[16][4];
#pragma unroll
        for (int i = 0; i < 16; i++)
#pragma unroll
            for (int j = 0; j < 4; j++) gacc[i][j] = 0.0f;

        for (int hh = 0; hh < 4; hh++) {
            const int t = l * 4 + hh;
            const int buf = t & 1;
            if (t > 0) { CP_WAIT0(); __syncthreads(); }   // W[t], outW[t], sa landed

            // ---- GEMM1: cacc = h @ W^T ----
            float cacc[16][4];
#pragma unroll
            for (int i = 0; i < 16; i++)
#pragma unroll
                for (int j = 0; j < 4; j++) cacc[i][j] = 0.0f;
            gemm1(smb + SM_HHI, smb + SM_HLO, smb + SM_PHI, smb + SM_PLO, cacc, R, lid);

            // ---- ei/ej partials from fragments + quad reduce ----
            float ei0 = 0.f, ej0 = 0.f, ei1 = 0.f, ej1 = 0.f;
            {
                const float* sav = sa + buf * 256;
#pragma unroll
                for (int q = 0; q < 16; q++) {
                    float s0 = sav[q * 8 + tg * 2], s1 = sav[q * 8 + tg * 2 + 1];
                    float d0 = sav[128 + q * 8 + tg * 2], d1 = sav[128 + q * 8 + tg * 2 + 1];
                    ei0 += cacc[q][0] * s0 + cacc[q][1] * s1;
                    ej0 += cacc[q][0] * d0 + cacc[q][1] * d1;
                    ei1 += cacc[q][2] * s0 + cacc[q][3] * s1;
                    ej1 += cacc[q][2] * d0 + cacc[q][3] * d1;
                }
#pragma unroll
                for (int o = 1; o < 4; o <<= 1) {
                    ei0 += __shfl_xor_sync(0xffffffffu, ei0, o);
                    ej0 += __shfl_xor_sync(0xffffffffu, ej0, o);
                    ei1 += __shfl_xor_sync(0xffffffffu, ei1, o);
                    ej1 += __shfl_xor_sync(0xffffffffu, ej1, o);
                }
            }

            __syncthreads();   // #1: all warps done reading W + sa[buf]
            if (t < 7) {       // prefetch next W (lands during softmax/hp/GEMM2)
                stage_pair(smb + SM_PHI, smb + SM_PLO,
                           (const uint4*)(g_Whi + ((t + 1) << 14)),
                           (const uint4*)(g_Wlo + ((t + 1) << 14)), tid);
                CP_COMMIT();
                sa[(buf ^ 1) * 256 + tid] = a_heads[(t + 1) * 256 + tid];
            }

            // ---- warp-local softmax for rows r0=R+group (batch0), r1=r0+8 (batch1) ----
            float att0[8], att1[8];
            {
                float mx0 = -1e30f, mx1 = -1e30f;
#pragma unroll
                for (int m = 0; m < 8; m++) {
                    float ejm0 = __shfl_sync(0xffffffffu, ej0, m * 4 + tg);
                    float ejm1 = __shfl_sync(0xffffffffu, ej1, m * 4 + tg);
                    float w = ewf[group * 8 + m];
                    int   ad = adji[group * 8 + m];
                    float v0 = 0.f, v1 = 0.f;
                    if (ad) {
                        float x0 = ei0 + ejm0; v0 = (x0 > 0.f ? x0 : 0.2f * x0) * w;
                        float x1 = ei1 + ejm1; v1 = (x1 > 0.f ? x1 : 0.2f * x1) * w;
                    }
                    att0[m] = v0; att1[m] = v1;
                    mx0 = fmaxf(mx0, v0); mx1 = fmaxf(mx1, v1);
                }
                float s0 = 0.f, s1 = 0.f;
#pragma unroll
                for (int m = 0; m < 8; m++) {
                    att0[m] = __expf(att0[m] - mx0); s0 += att0[m];
                    att1[m] = __expf(att1[m] - mx1); s1 += att1[m];
                }
                float i0 = 1.f / s0, i1 = 1.f / s1;
#pragma unroll
                for (int m = 0; m < 8; m++) { att0[m] *= i0; att1[m] *= i1; }
            }

            // ---- hp = elu(att @ Whh) via warp shuffles -> GEMM2 A-fragments ----
            uint32_t afHi[8][4], afLo[8][4];
#pragma unroll
            for (int q = 0; q < 16; q++) {
                float h0a = 0.f, h0b = 0.f, h1a = 0.f, h1b = 0.f;
#pragma unroll
                for (int m = 0; m < 8; m++) {
                    int src = m * 4 + tg;
                    float w0 = __shfl_sync(0xffffffffu, cacc[q][0], src);
                    float w1 = __shfl_sync(0xffffffffu, cacc[q][1], src);
                    float w2 = __shfl_sync(0xffffffffu, cacc[q][2], src);
                    float w3 = __shfl_sync(0xffffffffu, cacc[q][3], src);
                    h0a += att0[m] * w0; h0b += att0[m] * w1;
                    h1a += att1[m] * w2; h1b += att1[m] * w3;
                }
                h0a = h0a > 0.f ? h0a : (__expf(h0a) - 1.f);
                h0b = h0b > 0.f ? h0b : (__expf(h0b) - 1.f);
                h1a = h1a > 0.f ? h1a : (__expf(h1a) - 1.f);
                h1b = h1b > 0.f ? h1b : (__expf(h1b) - 1.f);
                uint32_t p0 = pack2(h0a, h0b), p1 = pack2(h1a, h1b);
                int kk = q >> 1, pos = (q & 1) << 1;
                afHi[kk][pos]     = p0;
                afHi[kk][pos + 1] = p1;
                afLo[kk][pos]     = pack2lo(h0a, bfu(p0), h0b, bfu(p0 >> 16));
                afLo[kk][pos + 1] = pack2lo(h1a, bfu(p1), h1b, bfu(p1 >> 16));
            }

            // ---- GEMM2: gacc += hp @ outW^T (A regs, B SMEM; jp-pair 3-pass) ----
            {
                const int lm = lid >> 3, lr = lid & 7;
                const uint32_t boff = (uint32_t)(lr + ((lm >> 1) << 3)) * PB + ((lm & 1) << 4);
                const uint32_t bS = smb + SM_S, bSL = smb + SM_SLO;
#pragma unroll 2
                for (int kk = 0; kk < 8; kk++) {
#pragma unroll
                    for (int jp2 = 0; jp2 < 4; jp2++) {
                        uint32_t bh0[4], bl0[4], bh1[4], bl1[4];
                        uint32_t bo0 = boff + (uint32_t)(jp2 * 32) * PB + kk * 32;
                        uint32_t bo1 = bo0 + (uint32_t)16 * PB;
                        ldsm4(bh0, bS + bo0);
                        ldsm4(bl0, bSL + bo0);
                        ldsm4(bh1, bS + bo1);
                        ldsm4(bl1, bSL + bo1);
                        mma_block(gacc, jp2 * 4, afHi[kk], afLo[kk], bh0, bl0, bh1, bl1);
                    }
                }
            }

            __syncthreads();   // #2: all warps done reading outW (S)
            if (t < 7) {       // prefetch next outW
                stage_pair(smb + SM_S, smb + SM_SLO,
                           (const uint4*)(g_OWhi + ((t + 1) << 14)),
                           (const uint4*)(g_OWlo + ((t + 1) << 14)), tid);
                CP_COMMIT();
            }
        } // heads

        // ---- residual + bias + LayerNorm (warp-local rows) ----
        {
            const float* lb = lnb + l * 384;
            int r0 = R + group, r1 = r0 + 8;
            float s0 = 0.f, q0 = 0.f, s1 = 0.f, q1 = 0.f;
            float x0v[16][2], x1v[16][2];
#pragma unroll
            for (int jp = 0; jp < 16; jp++) {
                int col = jp * 8 + tg * 2;
                uint32_t h0h = *(uint32_t*)(sm + SM_HHI + r0 * PB + col * 2);
                uint32_t h0l = *(uint32_t*)(sm + SM_HLO + r0 * PB + col * 2);
                uint32_t h1h = *(uint32_t*)(sm + SM_HHI + r1 * PB + col * 2);
                uint32_t h1l = *(uint32_t*)(sm + SM_HLO + r1 * PB + col * 2);
                float x00 = gacc[jp][0] + bfu(h0h) + bfu(h0l) + lb[col];
                float x01 = gacc[jp][1] + bfu(h0h >> 16) + bfu(h0l >> 16) + lb[col + 1];
                float x10 = gacc[jp][2] + bfu(h1h) + bfu(h1l) + lb[col];
                float x11 = gacc[jp][3] + bfu(h1h >> 16) + bfu(h1l >> 16) + lb[col + 1];
                x0v[jp][0] = x00; x0v[jp][1] = x01;
                x1v[jp][0] = x10; x1v[jp][1] = x11;
                s0 += x00 + x01; q0 += x00 * x00 + x01 * x01;
                s1 += x10 + x11; q1 += x10 * x10 + x11 * x11;
            }
#pragma unroll
            for (int o = 1; o < 4; o <<= 1) {
                s0 += __shfl_xor_sync(0xffffffffu, s0, o);
                q0 += __shfl_xor_sync(0xffffffffu, q0, o);
                s1 += __shfl_xor_sync(0xffffffffu, s1, o);
                q1 += __shfl_xor_sync(0xffffffffu, q1, o);
            }
            float mu0 = s0 * 0.0078125f, mu1 = s1 * 0.0078125f;
            float rstd0 = rsqrtf(q0 * 0.0078125f - mu0 * mu0 + 1e-5f);
            float rstd1 = rsqrtf(q1 * 0.0078125f - mu1 * mu1 + 1e-5f);
#pragma unroll
            for (int jp = 0; jp < 16; jp++) {
                int col = jp * 8 + tg * 2;
                float y00 = (x0v[jp][0] - mu0) * rstd0 * lb[128 + col]     + lb[256 + col];
                float y01 = (x0v[jp][1] - mu0) * rstd0 * lb[128 + col + 1] + lb[256 + col + 1];
                float y10 = (x1v[jp][0] - mu1) * rstd1 * lb[128 + col]     + lb[256 + col];
                float y11 = (x1v[jp][1] - mu1) * rstd1 * lb[128 + col + 1] + lb[256 + col + 1];
                if (l == 0) {
                    uint32_t w0 = pack2(y00, y01), w1 = pack2(y10, y11);
                    *(uint32_t*)(sm + SM_HHI + r0 * PB + col * 2) = w0;
                    *(uint32_t*)(sm + SM_HLO + r0 * PB + col * 2) =
                        pack2lo(y00, bfu(w0), y01, bfu(w0 >> 16));
                    *(uint32_t*)(sm + SM_HHI + r1 * PB + col * 2) = w1;
                    *(uint32_t*)(sm + SM_HLO + r1 * PB + col * 2) =
                        pack2lo(y10, bfu(w1), y11, bfu(w1 >> 16));
                } else {
                    *(float2*)(out + (b0 * 8 + r0) * 128 + col) = make_float2(y00, y01);
                    *(float2*)(out + (b0 * 8 + r1) * 128 + col) = make_float2(y10, y11);
                }
            }
            __syncwarp();   // h-tile writes visible to next-layer GEMM1 (warp-local)
        }
    } // layers
}

// ---------------------------------------------------------------------------
extern "C" void kernel_launch(void* const* d_in, const int* in_sizes, int n_in,
                              void* d_out, int out_size)
{
    const float* se      = (const float*)d_in[0];
    const float* te      = (const float*)d_in[1];
    const float* W_in    = (const float*)d_in[2];
    const float* b_in    = (const float*)d_in[3];
    const float* W_heads = (const float*)d_in[4];
    const float* a_heads = (const float*)d_in[5];
    const float* out_W   = (const float*)d_in[6];
    const float* out_b   = (const float*)d_in[7];
    const float* ln_s    = (const float*)d_in[8];
    const float* ln_b    = (const float*)d_in[9];
    const float* om_i    = (const float*)d_in[10];
    const float* om_c    = (const float*)d_in[11];
    const int*   adj     = (const int*)d_in[12];
    const int*   et      = (const int*)d_in[13];
    float* out = (float*)d_out;

    int B = in_sizes[0] / 128;
    size_t tail = (size_t)B * 8 * 128;

    prep<<<512, 256>>>(te, W_in, b_in, W_heads, out_W, om_i, om_c, adj, et, out + tail);

    cudaFuncSetAttribute(gat_tc, cudaFuncAttributeMaxDynamicSharedMemorySize, SMEM_BYTES);
    gat_tc<<<B / 16, 256, SMEM_BYTES>>>(se, a_heads, out_b, ln_s, ln_b,
                                        adj, et, om_i, om_c, out);
}

// round 10
// speedup vs baseline: 1.1900x; 1.1900x over previous
#include <cuda_runtime.h>
#include <cuda_bf16.h>
#include <cstdint>
#include <math.h>

// ===========================================================================
// TaskGraphGAT — round 9: R5 numerics/structure, halved CTA (128 thr, TB=8),
// single reusable weight buffer -> 109KB SMEM -> 2 CTAs/SM (occ 12.5->25%).
// ===========================================================================

#define PB   272        // bf16 tile pitch in BYTES (136 bf16), LDSM conflict-free

// ---------------- SMEM map (bytes) ----------------
#define SM_HHI   0          // h hi (64 x 136 bf16 = 17408 B)
#define SM_HLO   17408
#define SM_WHI   34816      // weight tile hi (W for GEMM1, then outW for GEMM2)
#define SM_WLO   69632
#define SM_SMALL 104448     // sa[256] | lnb[768] | ewf[64] | adji[64]
#define SMEM_BYTES 109056

// ---------------- device globals (written by prep) ----------------
__device__ float g_htask[8 * 128];
__device__ __align__(16) __nv_bfloat16 g_Whi[8 * 16384];
__device__ __align__(16) __nv_bfloat16 g_Wlo[8 * 16384];
__device__ __align__(16) __nv_bfloat16 g_OWhi[8 * 16384];
__device__ __align__(16) __nv_bfloat16 g_OWlo[8 * 16384];

// ---------------- helpers ----------------
__device__ __forceinline__ uint32_t smem_u32(const void* p) {
    uint32_t a;
    asm("{ .reg .u64 t; cvta.to.shared.u64 t, %1; cvt.u32.u64 %0, t; }" : "=r"(a) : "l"(p));
    return a;
}
__device__ __forceinline__ void ldsm4(uint32_t* r, uint32_t a) {
    asm volatile("ldmatrix.sync.aligned.m8n8.x4.shared.b16 {%0,%1,%2,%3}, [%4];"
                 : "=r"(r[0]), "=r"(r[1]), "=r"(r[2]), "=r"(r[3]) : "r"(a));
}
__device__ __forceinline__ void mma16816(float* c, const uint32_t* a, const uint32_t* b) {
    asm volatile(
        "mma.sync.aligned.m16n8k16.row.col.f32.bf16.bf16.f32 "
        "{%0,%1,%2,%3}, {%4,%5,%6,%7}, {%8,%9}, {%0,%1,%2,%3};"
        : "+f"(c[0]), "+f"(c[1]), "+f"(c[2]), "+f"(c[3])
        : "r"(a[0]), "r"(a[1]), "r"(a[2]), "r"(a[3]), "r"(b[0]), "r"(b[1]));
}
__device__ __forceinline__ void cpa16(uint32_t dst, const void* src) {
    asm volatile("cp.async.cg.shared.global [%0], [%1], 16;" :: "r"(dst), "l"(src));
}
#define CP_COMMIT() asm volatile("cp.async.commit_group;" ::: "memory")
#define CP_WAIT0()  asm volatile("cp.async.wait_group 0;" ::: "memory")

__device__ __forceinline__ uint32_t pack2(float x0, float x1) {
    __nv_bfloat162 v = __floats2bfloat162_rn(x0, x1);
    return *(uint32_t*)&v;
}
__device__ __forceinline__ uint32_t pack2lo(float x0, float h0, float x1, float h1) {
    __nv_bfloat162 v = __floats2bfloat162_rn(x0 - h0, x1 - h1);
    return *(uint32_t*)&v;
}
__device__ __forceinline__ float bfu(uint32_t u) {
    return __bfloat162float(__ushort_as_bfloat16((unsigned short)(u & 0xffff)));
}

// stage a hi/lo bf16 128x128 tile pair into pitched SMEM via cp.async (128 thr)
__device__ __forceinline__ void stage_tile(uint32_t dhi, uint32_t dlo,
                                           const uint4* shi, const uint4* slo, int tid) {
#pragma unroll
    for (int i = tid; i < 2048; i += 128) {
        uint32_t d = ((uint32_t)(i >> 4) * PB) + ((i & 15) << 4);
        cpa16(dhi + d, shi + i);
        cpa16(dlo + d, slo + i);
    }
}

// GEMM1: c[q][0..3] += A(hi/lo)[rows R..R+15] @ B(hi/lo)^T (R5-exact)
__device__ __forceinline__ void gemm1(uint32_t aHi, uint32_t aLo,
                                      uint32_t bHi, uint32_t bLo,
                                      float (&c)[16][4], int R, int lid) {
    const int lm = lid >> 3, lr = lid & 7;
    const uint32_t aoff = (uint32_t)(R + lr + ((lm & 1) << 3)) * PB + ((lm >> 1) << 4);
    const uint32_t boff = (uint32_t)(lr + ((lm >> 1) << 3)) * PB + ((lm & 1) << 4);
#pragma unroll 2
    for (int k = 0; k < 8; k++) {
        uint32_t ah[4], al[4];
        ldsm4(ah, aHi + aoff + k * 32);
        ldsm4(al, aLo + aoff + k * 32);
#pragma unroll
        for (int jp = 0; jp < 8; jp++) {
            uint32_t bh[4], bl[4];
            uint32_t bo = boff + (uint32_t)(jp * 16) * PB + k * 32;
            ldsm4(bh, bHi + bo);
            ldsm4(bl, bLo + bo);
            mma16816(c[2 * jp],     ah, bh);
            mma16816(c[2 * jp + 1], ah, bh + 2);
            mma16816(c[2 * jp],     ah, bl);
            mma16816(c[2 * jp + 1], ah, bl + 2);
            mma16816(c[2 * jp],     al, bh);
            mma16816(c[2 * jp + 1], al, bh + 2);
        }
    }
}

// ---------------- single setup kernel ----------------
__global__ void prep(const float* __restrict__ te, const float* __restrict__ W_in,
                     const float* __restrict__ b_in, const float* __restrict__ Wh,
                     const float* __restrict__ OW, const float* __restrict__ om_i,
                     const float* __restrict__ om_c, const int* __restrict__ adj,
                     const int* __restrict__ et, float* __restrict__ out_tail) {
    int idx = blockIdx.x * 256 + threadIdx.x;   // grid 512 -> 131072 = 8*16384
    {
        int t = idx >> 14, rem = idx & 16383, row = rem >> 7, col = rem & 127;
        float w = Wh[idx];                       // W_heads[t][g=row][f=col]
        __nv_bfloat16 h = __float2bfloat16(w);
        g_Whi[idx] = h;
        g_Wlo[idx] = __float2bfloat16(w - __bfloat162float(h));
        int l = t >> 2, hh = t & 3;              // out_W[l][c=row][hh*128+g=col]
        float w2 = OW[l * 65536 + row * 512 + hh * 128 + col];
        __nv_bfloat16 h2 = __float2bfloat16(w2);
        g_OWhi[idx] = h2;
        g_OWlo[idx] = __float2bfloat16(w2 - __bfloat162float(h2));
    }
    if (blockIdx.x == 0) {
        int t = threadIdx.x;
        if (t < 64) {
            float w = 0.f;
            if (adj[t]) { int e = et[t]; w = (e == 1) ? om_i[0] : ((e == 2) ? om_c[0] : 1.f); }
            out_tail[t] = w;
        }
        for (int i2 = t; i2 < 1024; i2 += 256) {
            int n = i2 >> 7, o = i2 & 127;
            const float* tr = te + n * 64;
            const float* wr = W_in + o * 64;
            float s = b_in[o];
#pragma unroll 8
            for (int d = 0; d < 64; d++) s += tr[d] * wr[d];
            g_htask[i2] = s;
        }
    }
}

// ---------------- main kernel ----------------
__global__ __launch_bounds__(128, 2)
void gat_tc(const float* __restrict__ se, const float* __restrict__ a_heads,
            const float* __restrict__ out_b, const float* __restrict__ ln_s,
            const float* __restrict__ ln_b, const int* __restrict__ adj,
            const int* __restrict__ et, const float* __restrict__ om_i,
            const float* __restrict__ om_c, float* __restrict__ out)
{
    extern __shared__ __align__(1024) unsigned char sm[];
    float* smf  = (float*)(sm + SM_SMALL);
    float* sa   = smf;                // [256] current head's a_src|a_dst
    float* lnb  = smf + 256;          // [2][384]: out_b | ln_scale | ln_bias
    float* ewf  = smf + 1024;         // [64]
    int*   adji = (int*)(smf + 1088); // [64]

    const uint32_t smb = smem_u32(sm);
    const uint32_t saA = smb + SM_SMALL;      // byte addr of sa
    const int tid = threadIdx.x;
    const int lid = tid & 31;
    const int wid = tid >> 5;                 // 0..3
    const int R     = wid << 4;               // warp's 16 rows (rows 0..63)
    const int group = lid >> 2;
    const int tg    = lid & 3;
    const long b0 = (long)blockIdx.x * 8;     // 8 batch elems per CTA

    // ---- prefetch head-0 W + sa ----
    stage_tile(smb + SM_WHI, smb + SM_WLO, (const uint4*)g_Whi, (const uint4*)g_Wlo, tid);
    if (tid < 64) cpa16(saA + tid * 16, a_heads + tid * 4);
    CP_COMMIT();

    // ---- small constants ----
    if (tid < 64) {
        int e = et[tid];
        ewf[tid] = adj[tid] ? ((e == 1) ? om_i[0] : ((e == 2) ? om_c[0] : 1.f)) : 0.f;
        adji[tid] = adj[tid];
    }
#pragma unroll
    for (int l = 0; l < 2; l++) {
        lnb[l * 384 + tid]       = out_b[l * 128 + tid];
        lnb[l * 384 + 128 + tid] = ln_s[l * 128 + tid];
        lnb[l * 384 + 256 + tid] = ln_b[l * 128 + tid];
    }

    // ---- build h tiles (hi/lo bf16): 64 rows, 2 threads per row ----
    {
        int r = tid & 63, f0 = (tid >> 6) * 64;
        const float* ser = se + (b0 + (r >> 3)) * 128;
        const float* htr = g_htask + (r & 7) * 128;
#pragma unroll 8
        for (int j = 0; j < 64; j += 2) {
            int f = f0 + j;
            float x0 = ser[f] + htr[f];
            float x1 = ser[f + 1] + htr[f + 1];
            uint32_t hiw = pack2(x0, x1);
            *(uint32_t*)(sm + SM_HHI + r * PB + f * 2) = hiw;
            *(uint32_t*)(sm + SM_HLO + r * PB + f * 2) =
                pack2lo(x0, bfu(hiw), x1, bfu(hiw >> 16));
        }
    }
    CP_WAIT0();
    __syncthreads();

    for (int l = 0; l < 2; l++) {
        float gacc[16][4];
#pragma unroll
        for (int i = 0; i < 16; i++)
#pragma unroll
            for (int j = 0; j < 4; j++) gacc[i][j] = 0.0f;

        for (int hh = 0; hh < 4; hh++) {
            const int t = l * 4 + hh;
            if (t > 0) { CP_WAIT0(); __syncthreads(); }   // W[t] + sa[t] landed

            // ---- GEMM1: cacc = h @ W^T ----
            float cacc[16][4];
#pragma unroll
            for (int i = 0; i < 16; i++)
#pragma unroll
                for (int j = 0; j < 4; j++) cacc[i][j] = 0.0f;
            gemm1(smb + SM_HHI, smb + SM_HLO, smb + SM_WHI, smb + SM_WLO, cacc, R, lid);

            // ---- ei/ej partials from fragments + quad reduce ----
            float ei0 = 0.f, ej0 = 0.f, ei1 = 0.f, ej1 = 0.f;
            {
#pragma unroll
                for (int q = 0; q < 16; q++) {
                    float s0 = sa[q * 8 + tg * 2], s1 = sa[q * 8 + tg * 2 + 1];
                    float d0 = sa[128 + q * 8 + tg * 2], d1 = sa[128 + q * 8 + tg * 2 + 1];
                    ei0 += cacc[q][0] * s0 + cacc[q][1] * s1;
                    ej0 += cacc[q][0] * d0 + cacc[q][1] * d1;
                    ei1 += cacc[q][2] * s0 + cacc[q][3] * s1;
                    ej1 += cacc[q][2] * d0 + cacc[q][3] * d1;
                }
#pragma unroll
                for (int o = 1; o < 4; o <<= 1) {
                    ei0 += __shfl_xor_sync(0xffffffffu, ei0, o);
                    ej0 += __shfl_xor_sync(0xffffffffu, ej0, o);
                    ei1 += __shfl_xor_sync(0xffffffffu, ei1, o);
                    ej1 += __shfl_xor_sync(0xffffffffu, ej1, o);
                }
            }

            __syncthreads();   // #1: all warps done reading W buf + sa
            // stage outW[t] into the same buffer; lands during softmax/hp
            stage_tile(smb + SM_WHI, smb + SM_WLO,
                       (const uint4*)(g_OWhi + (t << 14)),
                       (const uint4*)(g_OWlo + (t << 14)), tid);
            CP_COMMIT();

            // ---- warp-local softmax (rows r0=R+group batch0, r1=r0+8 batch1) ----
            float att0[8], att1[8];
            {
                float mx0 = -1e30f, mx1 = -1e30f;
#pragma unroll
                for (int m = 0; m < 8; m++) {
                    float ejm0 = __shfl_sync(0xffffffffu, ej0, m * 4 + tg);
                    float ejm1 = __shfl_sync(0xffffffffu, ej1, m * 4 + tg);
                    float w = ewf[group * 8 + m];
                    int   ad = adji[group * 8 + m];
                    float v0 = 0.f, v1 = 0.f;
                    if (ad) {
                        float x0 = ei0 + ejm0; v0 = (x0 > 0.f ? x0 : 0.2f * x0) * w;
                        float x1 = ei1 + ejm1; v1 = (x1 > 0.f ? x1 : 0.2f * x1) * w;
                    }
                    att0[m] = v0; att1[m] = v1;
                    mx0 = fmaxf(mx0, v0); mx1 = fmaxf(mx1, v1);
                }
                float s0 = 0.f, s1 = 0.f;
#pragma unroll
                for (int m = 0; m < 8; m++) {
                    att0[m] = __expf(att0[m] - mx0); s0 += att0[m];
                    att1[m] = __expf(att1[m] - mx1); s1 += att1[m];
                }
                float i0 = 1.f / s0, i1 = 1.f / s1;
#pragma unroll
                for (int m = 0; m < 8; m++) { att0[m] *= i0; att1[m] *= i1; }
            }

            // ---- hp = elu(att @ Whh) via warp shuffles -> GEMM2 A-fragments ----
            uint32_t afHi[8][4], afLo[8][4];
#pragma unroll
            for (int q = 0; q < 16; q++) {
                float h0a = 0.f, h0b = 0.f, h1a = 0.f, h1b = 0.f;
#pragma unroll
                for (int m = 0; m < 8; m++) {
                    int src = m * 4 + tg;
                    float w0 = __shfl_sync(0xffffffffu, cacc[q][0], src);
                    float w1 = __shfl_sync(0xffffffffu, cacc[q][1], src);
                    float w2 = __shfl_sync(0xffffffffu, cacc[q][2], src);
                    float w3 = __shfl_sync(0xffffffffu, cacc[q][3], src);
                    h0a += att0[m] * w0; h0b += att0[m] * w1;
                    h1a += att1[m] * w2; h1b += att1[m] * w3;
                }
                h0a = h0a > 0.f ? h0a : (__expf(h0a) - 1.f);
                h0b = h0b > 0.f ? h0b : (__expf(h0b) - 1.f);
                h1a = h1a > 0.f ? h1a : (__expf(h1a) - 1.f);
                h1b = h1b > 0.f ? h1b : (__expf(h1b) - 1.f);
                uint32_t p0 = pack2(h0a, h0b), p1 = pack2(h1a, h1b);
                int kk = q >> 1, pos = (q & 1) << 1;
                afHi[kk][pos]     = p0;
                afHi[kk][pos + 1] = p1;
                afLo[kk][pos]     = pack2lo(h0a, bfu(p0), h0b, bfu(p0 >> 16));
                afLo[kk][pos + 1] = pack2lo(h1a, bfu(p1), h1b, bfu(p1 >> 16));
            }

            CP_WAIT0();
            __syncthreads();   // #2: outW[t] landed

            // ---- GEMM2: gacc += hp @ outW^T (A regs, B SMEM) ----
            {
                const int lm = lid >> 3, lr = lid & 7;
                const uint32_t boff = (uint32_t)(lr + ((lm >> 1) << 3)) * PB + ((lm & 1) << 4);
                const uint32_t bS = smb + SM_WHI, bSL = smb + SM_WLO;
#pragma unroll
                for (int kk = 0; kk < 8; kk++) {
#pragma unroll
                    for (int jp = 0; jp < 8; jp++) {
                        uint32_t bh[4], bl[4];
                        uint32_t bo = boff + (uint32_t)(jp * 16) * PB + kk * 32;
                        ldsm4(bh, bS + bo);
                        ldsm4(bl, bSL + bo);
                        mma16816(gacc[2 * jp],     afHi[kk], bh);
                        mma16816(gacc[2 * jp + 1], afHi[kk], bh + 2);
                        mma16816(gacc[2 * jp],     afHi[kk], bl);
                        mma16816(gacc[2 * jp + 1], afHi[kk], bl + 2);
                        mma16816(gacc[2 * jp],     afLo[kk], bh);
                        mma16816(gacc[2 * jp + 1], afLo[kk], bh + 2);
                    }
                }
            }

            __syncthreads();   // #3: all warps done reading outW buf
            if (t < 7) {       // prefetch next head's W + sa (lands during LN/next top)
                stage_tile(smb + SM_WHI, smb + SM_WLO,
                           (const uint4*)(g_Whi + ((t + 1) << 14)),
                           (const uint4*)(g_Wlo + ((t + 1) << 14)), tid);
                if (tid < 64) cpa16(saA + tid * 16, a_heads + (t + 1) * 256 + tid * 4);
                CP_COMMIT();
            }
        } // heads

        // ---- residual + bias + LayerNorm (warp-local rows) ----
        {
            const float* lb = lnb + l * 384;
            int r0 = R + group, r1 = r0 + 8;
            float s0 = 0.f, q0 = 0.f, s1 = 0.f, q1 = 0.f;
            float x0v[16][2], x1v[16][2];
#pragma unroll
            for (int jp = 0; jp < 16; jp++) {
                int col = jp * 8 + tg * 2;
                uint32_t h0h = *(uint32_t*)(sm + SM_HHI + r0 * PB + col * 2);
                uint32_t h0l = *(uint32_t*)(sm + SM_HLO + r0 * PB + col * 2);
                uint32_t h1h = *(uint32_t*)(sm + SM_HHI + r1 * PB + col * 2);
                uint32_t h1l = *(uint32_t*)(sm + SM_HLO + r1 * PB + col * 2);
                float x00 = gacc[jp][0] + bfu(h0h) + bfu(h0l) + lb[col];
                float x01 = gacc[jp][1] + bfu(h0h >> 16) + bfu(h0l >> 16) + lb[col + 1];
                float x10 = gacc[jp][2] + bfu(h1h) + bfu(h1l) + lb[col];
                float x11 = gacc[jp][3] + bfu(h1h >> 16) + bfu(h1l >> 16) + lb[col + 1];
                x0v[jp][0] = x00; x0v[jp][1] = x01;
                x1v[jp][0] = x10; x1v[jp][1] = x11;
                s0 += x00 + x01; q0 += x00 * x00 + x01 * x01;
                s1 += x10 + x11; q1 += x10 * x10 + x11 * x11;
            }
#pragma unroll
            for (int o = 1; o < 4; o <<= 1) {
                s0 += __shfl_xor_sync(0xffffffffu, s0, o);
                q0 += __shfl_xor_sync(0xffffffffu, q0, o);
                s1 += __shfl_xor_sync(0xffffffffu, s1, o);
                q1 += __shfl_xor_sync(0xffffffffu, q1, o);
            }
            float mu0 = s0 * 0.0078125f, mu1 = s1 * 0.0078125f;
            float rstd0 = rsqrtf(q0 * 0.0078125f - mu0 * mu0 + 1e-5f);
            float rstd1 = rsqrtf(q1 * 0.0078125f - mu1 * mu1 + 1e-5f);
#pragma unroll
            for (int jp = 0; jp < 16; jp++) {
                int col = jp * 8 + tg * 2;
                float y00 = (x0v[jp][0] - mu0) * rstd0 * lb[128 + col]     + lb[256 + col];
                float y01 = (x0v[jp][1] - mu0) * rstd0 * lb[128 + col + 1] + lb[256 + col + 1];
                float y10 = (x1v[jp][0] - mu1) * rstd1 * lb[128 + col]     + lb[256 + col];
                float y11 = (x1v[jp][1] - mu1) * rstd1 * lb[128 + col + 1] + lb[256 + col + 1];
                if (l == 0) {
                    uint32_t w0 = pack2(y00, y01), w1 = pack2(y10, y11);
                    *(uint32_t*)(sm + SM_HHI + r0 * PB + col * 2) = w0;
                    *(uint32_t*)(sm + SM_HLO + r0 * PB + col * 2) =
                        pack2lo(y00, bfu(w0), y01, bfu(w0 >> 16));
                    *(uint32_t*)(sm + SM_HHI + r1 * PB + col * 2) = w1;
                    *(uint32_t*)(sm + SM_HLO + r1 * PB + col * 2) =
                        pack2lo(y10, bfu(w1), y11, bfu(w1 >> 16));
                } else {
                    *(float2*)(out + ((long)blockIdx.x * 64 + r0) * 128 + col) =
                        make_float2(y00, y01);
                    *(float2*)(out + ((long)blockIdx.x * 64 + r1) * 128 + col) =
                        make_float2(y10, y11);
                }
            }
            __syncwarp();   // h-tile writes visible to next-layer GEMM1 (warp-local)
        }
    } // layers
}

// ---------------------------------------------------------------------------
extern "C" void kernel_launch(void* const* d_in, const int* in_sizes, int n_in,
                              void* d_out, int out_size)
{
    const float* se      = (const float*)d_in[0];
    const float* te      = (const float*)d_in[1];
    const float* W_in    = (const float*)d_in[2];
    const float* b_in    = (const float*)d_in[3];
    const float* W_heads = (const float*)d_in[4];
    const float* a_heads = (const float*)d_in[5];
    const float* out_W   = (const float*)d_in[6];
    const float* out_b   = (const float*)d_in[7];
    const float* ln_s    = (const float*)d_in[8];
    const float* ln_b    = (const float*)d_in[9];
    const float* om_i    = (const float*)d_in[10];
    const float* om_c    = (const float*)d_in[11];
    const int*   adj     = (const int*)d_in[12];
    const int*   et      = (const int*)d_in[13];
    float* out = (float*)d_out;

    int B = in_sizes[0] / 128;
    size_t tail = (size_t)B * 8 * 128;

    prep<<<512, 256>>>(te, W_in, b_in, W_heads, out_W, om_i, om_c, adj, et, out + tail);

    cudaFuncSetAttribute(gat_tc, cudaFuncAttributeMaxDynamicSharedMemorySize, SMEM_BYTES);
    gat_tc<<<B / 8, 128, SMEM_BYTES>>>(se, a_heads, out_b, ln_s, ln_b,
                                       adj, et, om_i, om_c, out);
}

// round 11
// speedup vs baseline: 1.6222x; 1.3632x over previous
#include <cuda_runtime.h>
#include <cuda_fp16.h>
#include <cstdint>
#include <math.h>

// ===========================================================================
// TaskGraphGAT — round 10: fp16 asymmetric split (A = hi/lo fp16, weights =
// single fp16) -> 2 MMA products instead of 3, half the B-side LDSM, half the
// weight staging. Structure otherwise identical to R9/R10 best (754us).
// ===========================================================================

#define PB 272          // fp16 tile pitch in BYTES (136 halves), LDSM conflict-free

// ---------------- SMEM map (bytes) ----------------
#define SM_HHI   0          // h hi (64 x 136 fp16 = 17408 B)
#define SM_HLO   17408      // h lo
#define SM_W     34816      // W tile, single fp16 (128 x 136 = 34816 B)
#define SM_OW    69632      // outW tile, single fp16
#define SM_SMALL 104448     // sa[2][256] | lnb[768] | ewf[64] | adji[64]
#define SMEM_BYTES 110080

// ---------------- device globals (written by prep) ----------------
__device__ float g_htask[8 * 128];
__device__ __align__(16) __half g_W[8 * 16384];    // W_heads fp16
__device__ __align__(16) __half g_OW[8 * 16384];   // out_W rearranged fp16

// ---------------- helpers ----------------
__device__ __forceinline__ uint32_t smem_u32(const void* p) {
    uint32_t a;
    asm("{ .reg .u64 t; cvta.to.shared.u64 t, %1; cvt.u32.u64 %0, t; }" : "=r"(a) : "l"(p));
    return a;
}
__device__ __forceinline__ void ldsm4(uint32_t* r, uint32_t a) {
    asm volatile("ldmatrix.sync.aligned.m8n8.x4.shared.b16 {%0,%1,%2,%3}, [%4];"
                 : "=r"(r[0]), "=r"(r[1]), "=r"(r[2]), "=r"(r[3]) : "r"(a));
}
__device__ __forceinline__ void mma16816(float* c, const uint32_t* a, const uint32_t* b) {
    asm volatile(
        "mma.sync.aligned.m16n8k16.row.col.f32.f16.f16.f32 "
        "{%0,%1,%2,%3}, {%4,%5,%6,%7}, {%8,%9}, {%0,%1,%2,%3};"
        : "+f"(c[0]), "+f"(c[1]), "+f"(c[2]), "+f"(c[3])
        : "r"(a[0]), "r"(a[1]), "r"(a[2]), "r"(a[3]), "r"(b[0]), "r"(b[1]));
}
__device__ __forceinline__ void cpa16(uint32_t dst, const void* src) {
    asm volatile("cp.async.cg.shared.global [%0], [%1], 16;" :: "r"(dst), "l"(src));
}
#define CP_COMMIT() asm volatile("cp.async.commit_group;" ::: "memory")
#define CP_WAIT0()  asm volatile("cp.async.wait_group 0;" ::: "memory")

__device__ __forceinline__ uint32_t pack2(float x0, float x1) {
    __half2 v = __floats2half2_rn(x0, x1);
    return *(uint32_t*)&v;
}
__device__ __forceinline__ float hfu(uint32_t u) {
    return __half2float(__ushort_as_half((unsigned short)(u & 0xffff)));
}
__device__ __forceinline__ uint32_t pack2lo(float x0, float h0, float x1, float h1) {
    __half2 v = __floats2half2_rn(x0 - h0, x1 - h1);
    return *(uint32_t*)&v;
}

// stage a single fp16 128x128 tile into pitched SMEM via cp.async (128 thr)
__device__ __forceinline__ void stage_tile(uint32_t dst, const uint4* src, int tid) {
#pragma unroll
    for (int i = tid; i < 2048; i += 128) {
        uint32_t d = ((uint32_t)(i >> 4) * PB) + ((i & 15) << 4);
        cpa16(dst + d, src + i);
    }
}

// GEMM1: c[q][0..3] += (Ahi+Alo)[rows R..R+15] @ W^T ; W single fp16
__device__ __forceinline__ void gemm1(uint32_t aHi, uint32_t aLo, uint32_t bW,
                                      float (&c)[16][4], int R, int lid) {
    const int lm = lid >> 3, lr = lid & 7;
    const uint32_t aoff = (uint32_t)(R + lr + ((lm & 1) << 3)) * PB + ((lm >> 1) << 4);
    const uint32_t boff = (uint32_t)(lr + ((lm >> 1) << 3)) * PB + ((lm & 1) << 4);
#pragma unroll 2
    for (int k = 0; k < 8; k++) {
        uint32_t ah[4], al[4];
        ldsm4(ah, aHi + aoff + k * 32);
        ldsm4(al, aLo + aoff + k * 32);
#pragma unroll
        for (int jp = 0; jp < 8; jp++) {
            uint32_t bh[4];
            ldsm4(bh, bW + boff + (uint32_t)(jp * 16) * PB + k * 32);
            mma16816(c[2 * jp],     ah, bh);
            mma16816(c[2 * jp + 1], ah, bh + 2);
            mma16816(c[2 * jp],     al, bh);
            mma16816(c[2 * jp + 1], al, bh + 2);
        }
    }
}

// ---------------- single setup kernel ----------------
__global__ void prep(const float* __restrict__ te, const float* __restrict__ W_in,
                     const float* __restrict__ b_in, const float* __restrict__ Wh,
                     const float* __restrict__ OW, const float* __restrict__ om_i,
                     const float* __restrict__ om_c, const int* __restrict__ adj,
                     const int* __restrict__ et, float* __restrict__ out_tail) {
    int idx = blockIdx.x * 256 + threadIdx.x;   // grid 512 -> 131072 = 8*16384
    {
        int t = idx >> 14, rem = idx & 16383, row = rem >> 7, col = rem & 127;
        g_W[idx] = __float2half(Wh[idx]);        // W_heads[t][g=row][f=col]
        int l = t >> 2, hh = t & 3;              // out_W[l][c=row][hh*128+g=col]
        g_OW[idx] = __float2half(OW[l * 65536 + row * 512 + hh * 128 + col]);
    }
    if (blockIdx.x == 0) {
        int t = threadIdx.x;
        if (t < 64) {
            float w = 0.f;
            if (adj[t]) { int e = et[t]; w = (e == 1) ? om_i[0] : ((e == 2) ? om_c[0] : 1.f); }
            out_tail[t] = w;
        }
        for (int i2 = t; i2 < 1024; i2 += 256) {
            int n = i2 >> 7, o = i2 & 127;
            const float* tr = te + n * 64;
            const float* wr = W_in + o * 64;
            float s = b_in[o];
#pragma unroll 8
            for (int d = 0; d < 64; d++) s += tr[d] * wr[d];
            g_htask[i2] = s;
        }
    }
}

// ---------------- main kernel ----------------
__global__ __launch_bounds__(128, 2)
void gat_tc(const float* __restrict__ se, const float* __restrict__ a_heads,
            const float* __restrict__ out_b, const float* __restrict__ ln_s,
            const float* __restrict__ ln_b, const int* __restrict__ adj,
            const int* __restrict__ et, const float* __restrict__ om_i,
            const float* __restrict__ om_c, float* __restrict__ out)
{
    extern __shared__ __align__(1024) unsigned char sm[];
    float* smf  = (float*)(sm + SM_SMALL);
    float* sa   = smf;                // [2][256] a_src|a_dst double buffer
    float* lnb  = smf + 512;          // [2][384]: out_b | ln_scale | ln_bias
    float* ewf  = smf + 1280;         // [64]
    int*   adji = (int*)(smf + 1344); // [64]

    const uint32_t smb = smem_u32(sm);
    const uint32_t saA = smb + SM_SMALL;      // byte addr of sa
    const int tid = threadIdx.x;
    const int lid = tid & 31;
    const int wid = tid >> 5;                 // 0..3
    const int R     = wid << 4;               // warp's 16 rows
    const int group = lid >> 2;
    const int tg    = lid & 3;
    const long b0 = (long)blockIdx.x * 8;     // 8 batch elems per CTA

    // ---- prefetch head-0 W + outW + sa ----
    stage_tile(smb + SM_W,  (const uint4*)g_W,  tid);
    stage_tile(smb + SM_OW, (const uint4*)g_OW, tid);
    if (tid < 64) cpa16(saA + tid * 16, a_heads + tid * 4);
    CP_COMMIT();

    // ---- small constants ----
    if (tid < 64) {
        int e = et[tid];
        ewf[tid] = adj[tid] ? ((e == 1) ? om_i[0] : ((e == 2) ? om_c[0] : 1.f)) : 0.f;
        adji[tid] = adj[tid];
    }
#pragma unroll
    for (int l = 0; l < 2; l++) {
        lnb[l * 384 + tid]       = out_b[l * 128 + tid];
        lnb[l * 384 + 128 + tid] = ln_s[l * 128 + tid];
        lnb[l * 384 + 256 + tid] = ln_b[l * 128 + tid];
    }

    // ---- build h tiles (hi/lo fp16): 64 rows, 2 threads per row ----
    {
        int r = tid & 63, f0 = (tid >> 6) * 64;
        const float* ser = se + (b0 + (r >> 3)) * 128;
        const float* htr = g_htask + (r & 7) * 128;
#pragma unroll 8
        for (int j = 0; j < 64; j += 2) {
            int f = f0 + j;
            float x0 = ser[f] + htr[f];
            float x1 = ser[f + 1] + htr[f + 1];
            uint32_t hiw = pack2(x0, x1);
            *(uint32_t*)(sm + SM_HHI + r * PB + f * 2) = hiw;
            *(uint32_t*)(sm + SM_HLO + r * PB + f * 2) =
                pack2lo(x0, hfu(hiw), x1, hfu(hiw >> 16));
        }
    }
    CP_WAIT0();
    __syncthreads();

    for (int l = 0; l < 2; l++) {
        float gacc[16][4];
#pragma unroll
        for (int i = 0; i < 16; i++)
#pragma unroll
            for (int j = 0; j < 4; j++) gacc[i][j] = 0.0f;

        for (int hh = 0; hh < 4; hh++) {
            const int t = l * 4 + hh;
            const int buf = t & 1;
            if (t > 0) { CP_WAIT0(); __syncthreads(); }   // W[t], OW[t], sa[t] landed

            // ---- GEMM1: cacc = h @ W^T  (2-product fp16) ----
            float cacc[16][4];
#pragma unroll
            for (int i = 0; i < 16; i++)
#pragma unroll
                for (int j = 0; j < 4; j++) cacc[i][j] = 0.0f;
            gemm1(smb + SM_HHI, smb + SM_HLO, smb + SM_W, cacc, R, lid);

            // ---- ei/ej partials from fragments + quad reduce ----
            float ei0 = 0.f, ej0 = 0.f, ei1 = 0.f, ej1 = 0.f;
            {
                const float* sav = sa + buf * 256;
#pragma unroll
                for (int q = 0; q < 16; q++) {
                    float s0 = sav[q * 8 + tg * 2], s1 = sav[q * 8 + tg * 2 + 1];
                    float d0 = sav[128 + q * 8 + tg * 2], d1 = sav[128 + q * 8 + tg * 2 + 1];
                    ei0 += cacc[q][0] * s0 + cacc[q][1] * s1;
                    ej0 += cacc[q][0] * d0 + cacc[q][1] * d1;
                    ei1 += cacc[q][2] * s0 + cacc[q][3] * s1;
                    ej1 += cacc[q][2] * d0 + cacc[q][3] * d1;
                }
#pragma unroll
                for (int o = 1; o < 4; o <<= 1) {
                    ei0 += __shfl_xor_sync(0xffffffffu, ei0, o);
                    ej0 += __shfl_xor_sync(0xffffffffu, ej0, o);
                    ei1 += __shfl_xor_sync(0xffffffffu, ei1, o);
                    ej1 += __shfl_xor_sync(0xffffffffu, ej1, o);
                }
            }

            // ---- warp-local softmax (rows r0=R+group batch0, r1=r0+8 batch1) ----
            float att0[8], att1[8];
            {
                float mx0 = -1e30f, mx1 = -1e30f;
#pragma unroll
                for (int m = 0; m < 8; m++) {
                    float ejm0 = __shfl_sync(0xffffffffu, ej0, m * 4 + tg);
                    float ejm1 = __shfl_sync(0xffffffffu, ej1, m * 4 + tg);
                    float w = ewf[group * 8 + m];
                    int   ad = adji[group * 8 + m];
                    float v0 = 0.f, v1 = 0.f;
                    if (ad) {
                        float x0 = ei0 + ejm0; v0 = (x0 > 0.f ? x0 : 0.2f * x0) * w;
                        float x1 = ei1 + ejm1; v1 = (x1 > 0.f ? x1 : 0.2f * x1) * w;
                    }
                    att0[m] = v0; att1[m] = v1;
                    mx0 = fmaxf(mx0, v0); mx1 = fmaxf(mx1, v1);
                }
                float s0 = 0.f, s1 = 0.f;
#pragma unroll
                for (int m = 0; m < 8; m++) {
                    att0[m] = __expf(att0[m] - mx0); s0 += att0[m];
                    att1[m] = __expf(att1[m] - mx1); s1 += att1[m];
                }
                float i0 = 1.f / s0, i1 = 1.f / s1;
#pragma unroll
                for (int m = 0; m < 8; m++) { att0[m] *= i0; att1[m] *= i1; }
            }

            // ---- hp = elu(att @ Whh) via warp shuffles -> GEMM2 A-fragments ----
            uint32_t afHi[8][4], afLo[8][4];
#pragma unroll
            for (int q = 0; q < 16; q++) {
                float h0a = 0.f, h0b = 0.f, h1a = 0.f, h1b = 0.f;
#pragma unroll
                for (int m = 0; m < 8; m++) {
                    int src = m * 4 + tg;
                    float w0 = __shfl_sync(0xffffffffu, cacc[q][0], src);
                    float w1 = __shfl_sync(0xffffffffu, cacc[q][1], src);
                    float w2 = __shfl_sync(0xffffffffu, cacc[q][2], src);
                    float w3 = __shfl_sync(0xffffffffu, cacc[q][3], src);
                    h0a += att0[m] * w0; h0b += att0[m] * w1;
                    h1a += att1[m] * w2; h1b += att1[m] * w3;
                }
                h0a = h0a > 0.f ? h0a : (__expf(h0a) - 1.f);
                h0b = h0b > 0.f ? h0b : (__expf(h0b) - 1.f);
                h1a = h1a > 0.f ? h1a : (__expf(h1a) - 1.f);
                h1b = h1b > 0.f ? h1b : (__expf(h1b) - 1.f);
                uint32_t p0 = pack2(h0a, h0b), p1 = pack2(h1a, h1b);
                int kk = q >> 1, pos = (q & 1) << 1;
                afHi[kk][pos]     = p0;
                afHi[kk][pos + 1] = p1;
                afLo[kk][pos]     = pack2lo(h0a, hfu(p0), h0b, hfu(p0 >> 16));
                afLo[kk][pos + 1] = pack2lo(h1a, hfu(p1), h1b, hfu(p1 >> 16));
            }

            // ---- GEMM2: gacc += hp @ outW^T (A regs hi/lo, B = outW single) ----
            {
                const int lm = lid >> 3, lr = lid & 7;
                const uint32_t boff = (uint32_t)(lr + ((lm >> 1) << 3)) * PB + ((lm & 1) << 4);
                const uint32_t bS = smb + SM_OW;
#pragma unroll
                for (int kk = 0; kk < 8; kk++) {
#pragma unroll
                    for (int jp = 0; jp < 8; jp++) {
                        uint32_t bh[4];
                        ldsm4(bh, bS + boff + (uint32_t)(jp * 16) * PB + kk * 32);
                        mma16816(gacc[2 * jp],     afHi[kk], bh);
                        mma16816(gacc[2 * jp + 1], afHi[kk], bh + 2);
                        mma16816(gacc[2 * jp],     afLo[kk], bh);
                        mma16816(gacc[2 * jp + 1], afLo[kk], bh + 2);
                    }
                }
            }

            __syncthreads();   // all warps done with W, OW, sa[buf]
            if (t < 7) {       // prefetch next head (lands during LN / next GEMM1 top)
                stage_tile(smb + SM_W,  (const uint4*)(g_W  + ((t + 1) << 14)), tid);
                stage_tile(smb + SM_OW, (const uint4*)(g_OW + ((t + 1) << 14)), tid);
                if (tid < 64) cpa16(saA + (buf ^ 1) * 1024 + tid * 16,
                                    a_heads + (t + 1) * 256 + tid * 4);
                CP_COMMIT();
            }
        } // heads

        // ---- residual + bias + LayerNorm (warp-local rows) ----
        {
            const float* lb = lnb + l * 384;
            int r0 = R + group, r1 = r0 + 8;
            float s0 = 0.f, q0 = 0.f, s1 = 0.f, q1 = 0.f;
            float x0v[16][2], x1v[16][2];
#pragma unroll
            for (int jp = 0; jp < 16; jp++) {
                int col = jp * 8 + tg * 2;
                uint32_t h0h = *(uint32_t*)(sm + SM_HHI + r0 * PB + col * 2);
                uint32_t h0l = *(uint32_t*)(sm + SM_HLO + r0 * PB + col * 2);
                uint32_t h1h = *(uint32_t*)(sm + SM_HHI + r1 * PB + col * 2);
                uint32_t h1l = *(uint32_t*)(sm + SM_HLO + r1 * PB + col * 2);
                float x00 = gacc[jp][0] + hfu(h0h) + hfu(h0l) + lb[col];
                float x01 = gacc[jp][1] + hfu(h0h >> 16) + hfu(h0l >> 16) + lb[col + 1];
                float x10 = gacc[jp][2] + hfu(h1h) + hfu(h1l) + lb[col];
                float x11 = gacc[jp][3] + hfu(h1h >> 16) + hfu(h1l >> 16) + lb[col + 1];
                x0v[jp][0] = x00; x0v[jp][1] = x01;
                x1v[jp][0] = x10; x1v[jp][1] = x11;
                s0 += x00 + x01; q0 += x00 * x00 + x01 * x01;
                s1 += x10 + x11; q1 += x10 * x10 + x11 * x11;
            }
#pragma unroll
            for (int o = 1; o < 4; o <<= 1) {
                s0 += __shfl_xor_sync(0xffffffffu, s0, o);
                q0 += __shfl_xor_sync(0xffffffffu, q0, o);
                s1 += __shfl_xor_sync(0xffffffffu, s1, o);
                q1 += __shfl_xor_sync(0xffffffffu, q1, o);
            }
            float mu0 = s0 * 0.0078125f, mu1 = s1 * 0.0078125f;
            float rstd0 = rsqrtf(q0 * 0.0078125f - mu0 * mu0 + 1e-5f);
            float rstd1 = rsqrtf(q1 * 0.0078125f - mu1 * mu1 + 1e-5f);
#pragma unroll
            for (int jp = 0; jp < 16; jp++) {
                int col = jp * 8 + tg * 2;
                float y00 = (x0v[jp][0] - mu0) * rstd0 * lb[128 + col]     + lb[256 + col];
                float y01 = (x0v[jp][1] - mu0) * rstd0 * lb[128 + col + 1] + lb[256 + col + 1];
                float y10 = (x1v[jp][0] - mu1) * rstd1 * lb[128 + col]     + lb[256 + col];
                float y11 = (x1v[jp][1] - mu1) * rstd1 * lb[128 + col + 1] + lb[256 + col + 1];
                if (l == 0) {
                    uint32_t w0 = pack2(y00, y01), w1 = pack2(y10, y11);
                    *(uint32_t*)(sm + SM_HHI + r0 * PB + col * 2) = w0;
                    *(uint32_t*)(sm + SM_HLO + r0 * PB + col * 2) =
                        pack2lo(y00, hfu(w0), y01, hfu(w0 >> 16));
                    *(uint32_t*)(sm + SM_HHI + r1 * PB + col * 2) = w1;
                    *(uint32_t*)(sm + SM_HLO + r1 * PB + col * 2) =
                        pack2lo(y10, hfu(w1), y11, hfu(w1 >> 16));
                } else {
                    *(float2*)(out + ((long)blockIdx.x * 64 + r0) * 128 + col) =
                        make_float2(y00, y01);
                    *(float2*)(out + ((long)blockIdx.x * 64 + r1) * 128 + col) =
                        make_float2(y10, y11);
                }
            }
            __syncwarp();   // h-tile writes visible to next-layer GEMM1 (warp-local)
        }
    } // layers
}

// ---------------------------------------------------------------------------
extern "C" void kernel_launch(void* const* d_in, const int* in_sizes, int n_in,
                              void* d_out, int out_size)
{
    const float* se      = (const float*)d_in[0];
    const float* te      = (const float*)d_in[1];
    const float* W_in    = (const float*)d_in[2];
    const float* b_in    = (const float*)d_in[3];
    const float* W_heads = (const float*)d_in[4];
    const float* a_heads = (const float*)d_in[5];
    const float* out_W   = (const float*)d_in[6];
    const float* out_b   = (const float*)d_in[7];
    const float* ln_s    = (const float*)d_in[8];
    const float* ln_b    = (const float*)d_in[9];
    const float* om_i    = (const float*)d_in[10];
    const float* om_c    = (const float*)d_in[11];
    const int*   adj     = (const int*)d_in[12];
    const int*   et      = (const int*)d_in[13];
    float* out = (float*)d_out;

    int B = in_sizes[0] / 128;
    size_t tail = (size_t)B * 8 * 128;

    prep<<<512, 256>>>(te, W_in, b_in, W_heads, out_W, om_i, om_c, adj, et, out + tail);

    cudaFuncSetAttribute(gat_tc, cudaFuncAttributeMaxDynamicSharedMemorySize, SMEM_BYTES);
    gat_tc<<<B / 8, 128, SMEM_BYTES>>>(se, a_heads, out_b, ln_s, ln_b,
                                       adj, et, om_i, om_c, out);
}

// round 12
// speedup vs baseline: 1.8728x; 1.1544x over previous
#include <cuda_runtime.h>
#include <cuda_fp16.h>
#include <cstdint>
#include <math.h>

// ===========================================================================
// TaskGraphGAT — round 11: single-fp16 1-product GEMMs (A fp16, W fp16),
// half2-packed shuffles for hp, hi/lo h kept only for the residual path.
// Structure identical to R11 best (553us).
// ===========================================================================

#define PB 272          // fp16 tile pitch in BYTES (136 halves), LDSM conflict-free

// ---------------- SMEM map (bytes) ----------------
#define SM_HHI   0          // h hi (64 x 136 fp16 = 17408 B) -> GEMM1 A
#define SM_HLO   17408      // h lo (residual accuracy only)
#define SM_W     34816      // W tile fp16 (128 x 136 = 34816 B)
#define SM_OW    69632      // outW tile fp16
#define SM_SMALL 104448     // sa[2][256] | lnb[768] | ewf[64] | adji[64]
#define SMEM_BYTES 110080

// ---------------- device globals (written by prep) ----------------
__device__ float g_htask[8 * 128];
__device__ __align__(16) __half g_W[8 * 16384];    // W_heads fp16
__device__ __align__(16) __half g_OW[8 * 16384];   // out_W rearranged fp16

// ---------------- helpers ----------------
__device__ __forceinline__ uint32_t smem_u32(const void* p) {
    uint32_t a;
    asm("{ .reg .u64 t; cvta.to.shared.u64 t, %1; cvt.u32.u64 %0, t; }" : "=r"(a) : "l"(p));
    return a;
}
__device__ __forceinline__ void ldsm4(uint32_t* r, uint32_t a) {
    asm volatile("ldmatrix.sync.aligned.m8n8.x4.shared.b16 {%0,%1,%2,%3}, [%4];"
                 : "=r"(r[0]), "=r"(r[1]), "=r"(r[2]), "=r"(r[3]) : "r"(a));
}
__device__ __forceinline__ void mma16816(float* c, const uint32_t* a, const uint32_t* b) {
    asm volatile(
        "mma.sync.aligned.m16n8k16.row.col.f32.f16.f16.f32 "
        "{%0,%1,%2,%3}, {%4,%5,%6,%7}, {%8,%9}, {%0,%1,%2,%3};"
        : "+f"(c[0]), "+f"(c[1]), "+f"(c[2]), "+f"(c[3])
        : "r"(a[0]), "r"(a[1]), "r"(a[2]), "r"(a[3]), "r"(b[0]), "r"(b[1]));
}
__device__ __forceinline__ void cpa16(uint32_t dst, const void* src) {
    asm volatile("cp.async.cg.shared.global [%0], [%1], 16;" :: "r"(dst), "l"(src));
}
#define CP_COMMIT() asm volatile("cp.async.commit_group;" ::: "memory")
#define CP_WAIT0()  asm volatile("cp.async.wait_group 0;" ::: "memory")

__device__ __forceinline__ uint32_t pack2(float x0, float x1) {
    __half2 v = __floats2half2_rn(x0, x1);
    return *(uint32_t*)&v;
}
__device__ __forceinline__ float hfu(uint32_t u) {
    return __half2float(__ushort_as_half((unsigned short)(u & 0xffff)));
}
__device__ __forceinline__ uint32_t pack2lo(float x0, float h0, float x1, float h1) {
    __half2 v = __floats2half2_rn(x0 - h0, x1 - h1);
    return *(uint32_t*)&v;
}
__device__ __forceinline__ float2 unp2(uint32_t u) {
    return __half22float2(*(__half2*)&u);
}

// stage a single fp16 128x128 tile into pitched SMEM via cp.async (128 thr)
__device__ __forceinline__ void stage_tile(uint32_t dst, const uint4* src, int tid) {
#pragma unroll
    for (int i = tid; i < 2048; i += 128) {
        uint32_t d = ((uint32_t)(i >> 4) * PB) + ((i & 15) << 4);
        cpa16(dst + d, src + i);
    }
}

// GEMM1 (1 product): c[q][0..3] += A[rows R..R+15] @ W^T, A and W single fp16
__device__ __forceinline__ void gemm1(uint32_t aHi, uint32_t bW,
                                      float (&c)[16][4], int R, int lid) {
    const int lm = lid >> 3, lr = lid & 7;
    const uint32_t aoff = (uint32_t)(R + lr + ((lm & 1) << 3)) * PB + ((lm >> 1) << 4);
    const uint32_t boff = (uint32_t)(lr + ((lm >> 1) << 3)) * PB + ((lm & 1) << 4);
#pragma unroll 2
    for (int k = 0; k < 8; k++) {
        uint32_t ah[4];
        ldsm4(ah, aHi + aoff + k * 32);
#pragma unroll
        for (int jp = 0; jp < 8; jp++) {
            uint32_t bh[4];
            ldsm4(bh, bW + boff + (uint32_t)(jp * 16) * PB + k * 32);
            mma16816(c[2 * jp],     ah, bh);
            mma16816(c[2 * jp + 1], ah, bh + 2);
        }
    }
}

// ---------------- single setup kernel ----------------
__global__ void prep(const float* __restrict__ te, const float* __restrict__ W_in,
                     const float* __restrict__ b_in, const float* __restrict__ Wh,
                     const float* __restrict__ OW, const float* __restrict__ om_i,
                     const float* __restrict__ om_c, const int* __restrict__ adj,
                     const int* __restrict__ et, float* __restrict__ out_tail) {
    int idx = blockIdx.x * 256 + threadIdx.x;   // grid 512 -> 131072 = 8*16384
    {
        int t = idx >> 14, rem = idx & 16383, row = rem >> 7, col = rem & 127;
        g_W[idx] = __float2half(Wh[idx]);        // W_heads[t][g=row][f=col]
        int l = t >> 2, hh = t & 3;              // out_W[l][c=row][hh*128+g=col]
        g_OW[idx] = __float2half(OW[l * 65536 + row * 512 + hh * 128 + col]);
    }
    if (blockIdx.x == 0) {
        int t = threadIdx.x;
        if (t < 64) {
            float w = 0.f;
            if (adj[t]) { int e = et[t]; w = (e == 1) ? om_i[0] : ((e == 2) ? om_c[0] : 1.f); }
            out_tail[t] = w;
        }
        for (int i2 = t; i2 < 1024; i2 += 256) {
            int n = i2 >> 7, o = i2 & 127;
            const float* tr = te + n * 64;
            const float* wr = W_in + o * 64;
            float s = b_in[o];
#pragma unroll 8
            for (int d = 0; d < 64; d++) s += tr[d] * wr[d];
            g_htask[i2] = s;
        }
    }
}

// ---------------- main kernel ----------------
__global__ __launch_bounds__(128, 2)
void gat_tc(const float* __restrict__ se, const float* __restrict__ a_heads,
            const float* __restrict__ out_b, const float* __restrict__ ln_s,
            const float* __restrict__ ln_b, const int* __restrict__ adj,
            const int* __restrict__ et, const float* __restrict__ om_i,
            const float* __restrict__ om_c, float* __restrict__ out)
{
    extern __shared__ __align__(1024) unsigned char sm[];
    float* smf  = (float*)(sm + SM_SMALL);
    float* sa   = smf;                // [2][256] a_src|a_dst double buffer
    float* lnb  = smf + 512;          // [2][384]: out_b | ln_scale | ln_bias
    float* ewf  = smf + 1280;         // [64]
    int*   adji = (int*)(smf + 1344); // [64]

    const uint32_t smb = smem_u32(sm);
    const uint32_t saA = smb + SM_SMALL;      // byte addr of sa
    const int tid = threadIdx.x;
    const int lid = tid & 31;
    const int wid = tid >> 5;                 // 0..3
    const int R     = wid << 4;               // warp's 16 rows
    const int group = lid >> 2;
    const int tg    = lid & 3;
    const long b0 = (long)blockIdx.x * 8;     // 8 batch elems per CTA

    // ---- prefetch head-0 W + outW + sa ----
    stage_tile(smb + SM_W,  (const uint4*)g_W,  tid);
    stage_tile(smb + SM_OW, (const uint4*)g_OW, tid);
    if (tid < 64) cpa16(saA + tid * 16, a_heads + tid * 4);
    CP_COMMIT();

    // ---- small constants ----
    if (tid < 64) {
        int e = et[tid];
        ewf[tid] = adj[tid] ? ((e == 1) ? om_i[0] : ((e == 2) ? om_c[0] : 1.f)) : 0.f;
        adji[tid] = adj[tid];
    }
#pragma unroll
    for (int l = 0; l < 2; l++) {
        lnb[l * 384 + tid]       = out_b[l * 128 + tid];
        lnb[l * 384 + 128 + tid] = ln_s[l * 128 + tid];
        lnb[l * 384 + 256 + tid] = ln_b[l * 128 + tid];
    }

    // ---- build h tiles (hi used by GEMM1; lo only for residual): 64 rows ----
    {
        int r = tid & 63, f0 = (tid >> 6) * 64;
        const float* ser = se + (b0 + (r >> 3)) * 128;
        const float* htr = g_htask + (r & 7) * 128;
#pragma unroll 8
        for (int j = 0; j < 64; j += 2) {
            int f = f0 + j;
            float x0 = ser[f] + htr[f];
            float x1 = ser[f + 1] + htr[f + 1];
            uint32_t hiw = pack2(x0, x1);
            *(uint32_t*)(sm + SM_HHI + r * PB + f * 2) = hiw;
            *(uint32_t*)(sm + SM_HLO + r * PB + f * 2) =
                pack2lo(x0, hfu(hiw), x1, hfu(hiw >> 16));
        }
    }
    CP_WAIT0();
    __syncthreads();

    for (int l = 0; l < 2; l++) {
        float gacc[16][4];
#pragma unroll
        for (int i = 0; i < 16; i++)
#pragma unroll
            for (int j = 0; j < 4; j++) gacc[i][j] = 0.0f;

        for (int hh = 0; hh < 4; hh++) {
            const int t = l * 4 + hh;
            const int buf = t & 1;
            if (t > 0) { CP_WAIT0(); __syncthreads(); }   // W[t], OW[t], sa[t] landed

            // ---- GEMM1: cacc = h @ W^T  (single product) ----
            float cacc[16][4];
#pragma unroll
            for (int i = 0; i < 16; i++)
#pragma unroll
                for (int j = 0; j < 4; j++) cacc[i][j] = 0.0f;
            gemm1(smb + SM_HHI, smb + SM_W, cacc, R, lid);

            // ---- ei/ej partials from fp32 fragments + quad reduce ----
            float ei0 = 0.f, ej0 = 0.f, ei1 = 0.f, ej1 = 0.f;
            {
                const float* sav = sa + buf * 256;
#pragma unroll
                for (int q = 0; q < 16; q++) {
                    float s0 = sav[q * 8 + tg * 2], s1 = sav[q * 8 + tg * 2 + 1];
                    float d0 = sav[128 + q * 8 + tg * 2], d1 = sav[128 + q * 8 + tg * 2 + 1];
                    ei0 += cacc[q][0] * s0 + cacc[q][1] * s1;
                    ej0 += cacc[q][0] * d0 + cacc[q][1] * d1;
                    ei1 += cacc[q][2] * s0 + cacc[q][3] * s1;
                    ej1 += cacc[q][2] * d0 + cacc[q][3] * d1;
                }
#pragma unroll
                for (int o = 1; o < 4; o <<= 1) {
                    ei0 += __shfl_xor_sync(0xffffffffu, ei0, o);
                    ej0 += __shfl_xor_sync(0xffffffffu, ej0, o);
                    ei1 += __shfl_xor_sync(0xffffffffu, ei1, o);
                    ej1 += __shfl_xor_sync(0xffffffffu, ej1, o);
                }
            }

            // ---- pack Whh fragments to half2 (the GEMM2 fp16 quantization) ----
            uint32_t pc01[16], pc23[16];
#pragma unroll
            for (int q = 0; q < 16; q++) {
                pc01[q] = pack2(cacc[q][0], cacc[q][1]);
                pc23[q] = pack2(cacc[q][2], cacc[q][3]);
            }

            // ---- warp-local softmax (rows r0=R+group batch0, r1=r0+8 batch1) ----
            float att0[8], att1[8];
            {
                float mx0 = -1e30f, mx1 = -1e30f;
#pragma unroll
                for (int m = 0; m < 8; m++) {
                    float ejm0 = __shfl_sync(0xffffffffu, ej0, m * 4 + tg);
                    float ejm1 = __shfl_sync(0xffffffffu, ej1, m * 4 + tg);
                    float w = ewf[group * 8 + m];
                    int   ad = adji[group * 8 + m];
                    float v0 = 0.f, v1 = 0.f;
                    if (ad) {
                        float x0 = ei0 + ejm0; v0 = (x0 > 0.f ? x0 : 0.2f * x0) * w;
                        float x1 = ei1 + ejm1; v1 = (x1 > 0.f ? x1 : 0.2f * x1) * w;
                    }
                    att0[m] = v0; att1[m] = v1;
                    mx0 = fmaxf(mx0, v0); mx1 = fmaxf(mx1, v1);
                }
                float s0 = 0.f, s1 = 0.f;
#pragma unroll
                for (int m = 0; m < 8; m++) {
                    att0[m] = __expf(att0[m] - mx0); s0 += att0[m];
                    att1[m] = __expf(att1[m] - mx1); s1 += att1[m];
                }
                float i0 = 1.f / s0, i1 = 1.f / s1;
#pragma unroll
                for (int m = 0; m < 8; m++) { att0[m] *= i0; att1[m] *= i1; }
            }

            // ---- hp = elu(att @ Whh): packed shuffles (2/m instead of 4) ----
            uint32_t afHi[8][4];
#pragma unroll
            for (int q = 0; q < 16; q++) {
                float h0a = 0.f, h0b = 0.f, h1a = 0.f, h1b = 0.f;
#pragma unroll
                for (int m = 0; m < 8; m++) {
                    int src = m * 4 + tg;
                    uint32_t w01 = __shfl_sync(0xffffffffu, pc01[q], src);
                    uint32_t w23 = __shfl_sync(0xffffffffu, pc23[q], src);
                    float2 f01 = unp2(w01);
                    float2 f23 = unp2(w23);
                    h0a += att0[m] * f01.x; h0b += att0[m] * f01.y;
                    h1a += att1[m] * f23.x; h1b += att1[m] * f23.y;
                }
                h0a = h0a > 0.f ? h0a : (__expf(h0a) - 1.f);
                h0b = h0b > 0.f ? h0b : (__expf(h0b) - 1.f);
                h1a = h1a > 0.f ? h1a : (__expf(h1a) - 1.f);
                h1b = h1b > 0.f ? h1b : (__expf(h1b) - 1.f);
                int kk = q >> 1, pos = (q & 1) << 1;
                afHi[kk][pos]     = pack2(h0a, h0b);
                afHi[kk][pos + 1] = pack2(h1a, h1b);
            }

            // ---- GEMM2: gacc += hp @ outW^T (single product, A regs) ----
            {
                const int lm = lid >> 3, lr = lid & 7;
                const uint32_t boff = (uint32_t)(lr + ((lm >> 1) << 3)) * PB + ((lm & 1) << 4);
                const uint32_t bS = smb + SM_OW;
#pragma unroll
                for (int kk = 0; kk < 8; kk++) {
#pragma unroll
                    for (int jp = 0; jp < 8; jp++) {
                        uint32_t bh[4];
                        ldsm4(bh, bS + boff + (uint32_t)(jp * 16) * PB + kk * 32);
                        mma16816(gacc[2 * jp],     afHi[kk], bh);
                        mma16816(gacc[2 * jp + 1], afHi[kk], bh + 2);
                    }
                }
            }

            __syncthreads();   // all warps done with W, OW, sa[buf]
            if (t < 7) {       // prefetch next head (lands during LN / next GEMM1)
                stage_tile(smb + SM_W,  (const uint4*)(g_W  + ((t + 1) << 14)), tid);
                stage_tile(smb + SM_OW, (const uint4*)(g_OW + ((t + 1) << 14)), tid);
                if (tid < 64) cpa16(saA + (buf ^ 1) * 1024 + tid * 16,
                                    a_heads + (t + 1) * 256 + tid * 4);
                CP_COMMIT();
            }
        } // heads

        // ---- residual + bias + LayerNorm (warp-local rows; h = hi+lo) ----
        {
            const float* lb = lnb + l * 384;
            int r0 = R + group, r1 = r0 + 8;
            float s0 = 0.f, q0 = 0.f, s1 = 0.f, q1 = 0.f;
            float x0v[16][2], x1v[16][2];
#pragma unroll
            for (int jp = 0; jp < 16; jp++) {
                int col = jp * 8 + tg * 2;
                uint32_t h0h = *(uint32_t*)(sm + SM_HHI + r0 * PB + col * 2);
                uint32_t h0l = *(uint32_t*)(sm + SM_HLO + r0 * PB + col * 2);
                uint32_t h1h = *(uint32_t*)(sm + SM_HHI + r1 * PB + col * 2);
                uint32_t h1l = *(uint32_t*)(sm + SM_HLO + r1 * PB + col * 2);
                float x00 = gacc[jp][0] + hfu(h0h) + hfu(h0l) + lb[col];
                float x01 = gacc[jp][1] + hfu(h0h >> 16) + hfu(h0l >> 16) + lb[col + 1];
                float x10 = gacc[jp][2] + hfu(h1h) + hfu(h1l) + lb[col];
                float x11 = gacc[jp][3] + hfu(h1h >> 16) + hfu(h1l >> 16) + lb[col + 1];
                x0v[jp][0] = x00; x0v[jp][1] = x01;
                x1v[jp][0] = x10; x1v[jp][1] = x11;
                s0 += x00 + x01; q0 += x00 * x00 + x01 * x01;
                s1 += x10 + x11; q1 += x10 * x10 + x11 * x11;
            }
#pragma unroll
            for (int o = 1; o < 4; o <<= 1) {
                s0 += __shfl_xor_sync(0xffffffffu, s0, o);
                q0 += __shfl_xor_sync(0xffffffffu, q0, o);
                s1 += __shfl_xor_sync(0xffffffffu, s1, o);
                q1 += __shfl_xor_sync(0xffffffffu, q1, o);
            }
            float mu0 = s0 * 0.0078125f, mu1 = s1 * 0.0078125f;
            float rstd0 = rsqrtf(q0 * 0.0078125f - mu0 * mu0 + 1e-5f);
            float rstd1 = rsqrtf(q1 * 0.0078125f - mu1 * mu1 + 1e-5f);
#pragma unroll
            for (int jp = 0; jp < 16; jp++) {
                int col = jp * 8 + tg * 2;
                float y00 = (x0v[jp][0] - mu0) * rstd0 * lb[128 + col]     + lb[256 + col];
                float y01 = (x0v[jp][1] - mu0) * rstd0 * lb[128 + col + 1] + lb[256 + col + 1];
                float y10 = (x1v[jp][0] - mu1) * rstd1 * lb[128 + col]     + lb[256 + col];
                float y11 = (x1v[jp][1] - mu1) * rstd1 * lb[128 + col + 1] + lb[256 + col + 1];
                if (l == 0) {
                    uint32_t w0 = pack2(y00, y01), w1 = pack2(y10, y11);
                    *(uint32_t*)(sm + SM_HHI + r0 * PB + col * 2) = w0;
                    *(uint32_t*)(sm + SM_HLO + r0 * PB + col * 2) =
                        pack2lo(y00, hfu(w0), y01, hfu(w0 >> 16));
                    *(uint32_t*)(sm + SM_HHI + r1 * PB + col * 2) = w1;
                    *(uint32_t*)(sm + SM_HLO + r1 * PB + col * 2) =
                        pack2lo(y10, hfu(w1), y11, hfu(w1 >> 16));
                } else {
                    *(float2*)(out + ((long)blockIdx.x * 64 + r0) * 128 + col) =
                        make_float2(y00, y01);
                    *(float2*)(out + ((long)blockIdx.x * 64 + r1) * 128 + col) =
                        make_float2(y10, y11);
                }
            }
            __syncwarp();   // h-tile writes visible to next-layer GEMM1 (warp-local)
        }
    } // layers
}

// ---------------------------------------------------------------------------
extern "C" void kernel_launch(void* const* d_in, const int* in_sizes, int n_in,
                              void* d_out, int out_size)
{
    const float* se      = (const float*)d_in[0];
    const float* te      = (const float*)d_in[1];
    const float* W_in    = (const float*)d_in[2];
    const float* b_in    = (const float*)d_in[3];
    const float* W_heads = (const float*)d_in[4];
    const float* a_heads = (const float*)d_in[5];
    const float* out_W   = (const float*)d_in[6];
    const float* out_b   = (const float*)d_in[7];
    const float* ln_s    = (const float*)d_in[8];
    const float* ln_b    = (const float*)d_in[9];
    const float* om_i    = (const float*)d_in[10];
    const float* om_c    = (const float*)d_in[11];
    const int*   adj     = (const int*)d_in[12];
    const int*   et      = (const int*)d_in[13];
    float* out = (float*)d_out;

    int B = in_sizes[0] / 128;
    size_t tail = (size_t)B * 8 * 128;

    prep<<<512, 256>>>(te, W_in, b_in, W_heads, out_W, om_i, om_c, adj, et, out + tail);

    cudaFuncSetAttribute(gat_tc, cudaFuncAttributeMaxDynamicSharedMemorySize, SMEM_BYTES);
    gat_tc<<<B / 8, 128, SMEM_BYTES>>>(se, a_heads, out_b, ln_s, ln_b,
                                       adj, et, om_i, om_c, out);
}

// round 13
// speedup vs baseline: 2.1134x; 1.1285x over previous
#include <cuda_runtime.h>
#include <cuda_fp16.h>
#include <cstdint>
#include <math.h>

// ===========================================================================
// TaskGraphGAT — round 12: hp phase as m16n8k16 MMA (batches stacked along k),
// B-fragments gathered from Whh C-fragments via 4 SHFL + 2 PRMT per tile.
// Removes ~35% of issue slots vs R12 best (479us). Rest identical.
// ===========================================================================

#define PB 272          // fp16 tile pitch in BYTES (136 halves), LDSM conflict-free

// ---------------- SMEM map (bytes) ----------------
#define SM_HHI   0          // h hi (64 x 136 fp16 = 17408 B) -> GEMM1 A
#define SM_HLO   17408      // h lo (residual accuracy only)
#define SM_W     34816      // W tile fp16 (128 x 136 = 34816 B)
#define SM_OW    69632      // outW tile fp16
#define SM_SMALL 104448     // sa[2][256] | lnb[768] | ewf[64] | adji[64]
#define SMEM_BYTES 110080

// ---------------- device globals (written by prep) ----------------
__device__ float g_htask[8 * 128];
__device__ __align__(16) __half g_W[8 * 16384];    // W_heads fp16
__device__ __align__(16) __half g_OW[8 * 16384];   // out_W rearranged fp16

// ---------------- helpers ----------------
__device__ __forceinline__ uint32_t smem_u32(const void* p) {
    uint32_t a;
    asm("{ .reg .u64 t; cvta.to.shared.u64 t, %1; cvt.u32.u64 %0, t; }" : "=r"(a) : "l"(p));
    return a;
}
__device__ __forceinline__ void ldsm4(uint32_t* r, uint32_t a) {
    asm volatile("ldmatrix.sync.aligned.m8n8.x4.shared.b16 {%0,%1,%2,%3}, [%4];"
                 : "=r"(r[0]), "=r"(r[1]), "=r"(r[2]), "=r"(r[3]) : "r"(a));
}
__device__ __forceinline__ void mma16816(float* c, const uint32_t* a, const uint32_t* b) {
    asm volatile(
        "mma.sync.aligned.m16n8k16.row.col.f32.f16.f16.f32 "
        "{%0,%1,%2,%3}, {%4,%5,%6,%7}, {%8,%9}, {%0,%1,%2,%3};"
        : "+f"(c[0]), "+f"(c[1]), "+f"(c[2]), "+f"(c[3])
        : "r"(a[0]), "r"(a[1]), "r"(a[2]), "r"(a[3]), "r"(b[0]), "r"(b[1]));
}
__device__ __forceinline__ void cpa16(uint32_t dst, const void* src) {
    asm volatile("cp.async.cg.shared.global [%0], [%1], 16;" :: "r"(dst), "l"(src));
}
#define CP_COMMIT() asm volatile("cp.async.commit_group;" ::: "memory")
#define CP_WAIT0()  asm volatile("cp.async.wait_group 0;" ::: "memory")

__device__ __forceinline__ uint32_t pack2(float x0, float x1) {
    __half2 v = __floats2half2_rn(x0, x1);
    return *(uint32_t*)&v;
}
__device__ __forceinline__ float hfu(uint32_t u) {
    return __half2float(__ushort_as_half((unsigned short)(u & 0xffff)));
}
__device__ __forceinline__ uint32_t pack2lo(float x0, float h0, float x1, float h1) {
    __half2 v = __floats2half2_rn(x0 - h0, x1 - h1);
    return *(uint32_t*)&v;
}

// stage a single fp16 128x128 tile into pitched SMEM via cp.async (128 thr)
__device__ __forceinline__ void stage_tile(uint32_t dst, const uint4* src, int tid) {
#pragma unroll
    for (int i = tid; i < 2048; i += 128) {
        uint32_t d = ((uint32_t)(i >> 4) * PB) + ((i & 15) << 4);
        cpa16(dst + d, src + i);
    }
}

// GEMM1 (1 product): c[q][0..3] += A[rows R..R+15] @ W^T, A and W single fp16
__device__ __forceinline__ void gemm1(uint32_t aHi, uint32_t bW,
                                      float (&c)[16][4], int R, int lid) {
    const int lm = lid >> 3, lr = lid & 7;
    const uint32_t aoff = (uint32_t)(R + lr + ((lm & 1) << 3)) * PB + ((lm >> 1) << 4);
    const uint32_t boff = (uint32_t)(lr + ((lm >> 1) << 3)) * PB + ((lm & 1) << 4);
#pragma unroll 2
    for (int k = 0; k < 8; k++) {
        uint32_t ah[4];
        ldsm4(ah, aHi + aoff + k * 32);
#pragma unroll
        for (int jp = 0; jp < 8; jp++) {
            uint32_t bh[4];
            ldsm4(bh, bW + boff + (uint32_t)(jp * 16) * PB + k * 32);
            mma16816(c[2 * jp],     ah, bh);
            mma16816(c[2 * jp + 1], ah, bh + 2);
        }
    }
}

// ---------------- single setup kernel ----------------
__global__ void prep(const float* __restrict__ te, const float* __restrict__ W_in,
                     const float* __restrict__ b_in, const float* __restrict__ Wh,
                     const float* __restrict__ OW, const float* __restrict__ om_i,
                     const float* __restrict__ om_c, const int* __restrict__ adj,
                     const int* __restrict__ et, float* __restrict__ out_tail) {
    int idx = blockIdx.x * 256 + threadIdx.x;   // grid 512 -> 131072 = 8*16384
    {
        int t = idx >> 14, rem = idx & 16383, row = rem >> 7, col = rem & 127;
        g_W[idx] = __float2half(Wh[idx]);        // W_heads[t][g=row][f=col]
        int l = t >> 2, hh = t & 3;              // out_W[l][c=row][hh*128+g=col]
        g_OW[idx] = __float2half(OW[l * 65536 + row * 512 + hh * 128 + col]);
    }
    if (blockIdx.x == 0) {
        int t = threadIdx.x;
        if (t < 64) {
            float w = 0.f;
            if (adj[t]) { int e = et[t]; w = (e == 1) ? om_i[0] : ((e == 2) ? om_c[0] : 1.f); }
            out_tail[t] = w;
        }
        for (int i2 = t; i2 < 1024; i2 += 256) {
            int n = i2 >> 7, o = i2 & 127;
            const float* tr = te + n * 64;
            const float* wr = W_in + o * 64;
            float s = b_in[o];
#pragma unroll 8
            for (int d = 0; d < 64; d++) s += tr[d] * wr[d];
            g_htask[i2] = s;
        }
    }
}

// ---------------- main kernel ----------------
__global__ __launch_bounds__(128, 2)
void gat_tc(const float* __restrict__ se, const float* __restrict__ a_heads,
            const float* __restrict__ out_b, const float* __restrict__ ln_s,
            const float* __restrict__ ln_b, const int* __restrict__ adj,
            const int* __restrict__ et, const float* __restrict__ om_i,
            const float* __restrict__ om_c, float* __restrict__ out)
{
    extern __shared__ __align__(1024) unsigned char sm[];
    float* smf  = (float*)(sm + SM_SMALL);
    float* sa   = smf;                // [2][256] a_src|a_dst double buffer
    float* lnb  = smf + 512;          // [2][384]: out_b | ln_scale | ln_bias
    float* ewf  = smf + 1280;         // [64]
    int*   adji = (int*)(smf + 1344); // [64]

    const uint32_t smb = smem_u32(sm);
    const uint32_t saA = smb + SM_SMALL;      // byte addr of sa
    const int tid = threadIdx.x;
    const int lid = tid & 31;
    const int wid = tid >> 5;                 // 0..3
    const int R     = wid << 4;               // warp's 16 rows
    const int group = lid >> 2;
    const int tg    = lid & 3;
    const long b0 = (long)blockIdx.x * 8;     // 8 batch elems per CTA

    // ---- prefetch head-0 W + outW + sa ----
    stage_tile(smb + SM_W,  (const uint4*)g_W,  tid);
    stage_tile(smb + SM_OW, (const uint4*)g_OW, tid);
    if (tid < 64) cpa16(saA + tid * 16, a_heads + tid * 4);
    CP_COMMIT();

    // ---- small constants ----
    if (tid < 64) {
        int e = et[tid];
        ewf[tid] = adj[tid] ? ((e == 1) ? om_i[0] : ((e == 2) ? om_c[0] : 1.f)) : 0.f;
        adji[tid] = adj[tid];
    }
#pragma unroll
    for (int l = 0; l < 2; l++) {
        lnb[l * 384 + tid]       = out_b[l * 128 + tid];
        lnb[l * 384 + 128 + tid] = ln_s[l * 128 + tid];
        lnb[l * 384 + 256 + tid] = ln_b[l * 128 + tid];
    }

    // ---- build h tiles (hi used by GEMM1; lo only for residual): 64 rows ----
    {
        int r = tid & 63, f0 = (tid >> 6) * 64;
        const float* ser = se + (b0 + (r >> 3)) * 128;
        const float* htr = g_htask + (r & 7) * 128;
#pragma unroll 8
        for (int j = 0; j < 64; j += 2) {
            int f = f0 + j;
            float x0 = ser[f] + htr[f];
            float x1 = ser[f + 1] + htr[f + 1];
            uint32_t hiw = pack2(x0, x1);
            *(uint32_t*)(sm + SM_HHI + r * PB + f * 2) = hiw;
            *(uint32_t*)(sm + SM_HLO + r * PB + f * 2) =
                pack2lo(x0, hfu(hiw), x1, hfu(hiw >> 16));
        }
    }
    CP_WAIT0();
    __syncthreads();

    for (int l = 0; l < 2; l++) {
        float gacc[16][4];
#pragma unroll
        for (int i = 0; i < 16; i++)
#pragma unroll
            for (int j = 0; j < 4; j++) gacc[i][j] = 0.0f;

        for (int hh = 0; hh < 4; hh++) {
            const int t = l * 4 + hh;
            const int buf = t & 1;
            if (t > 0) { CP_WAIT0(); __syncthreads(); }   // W[t], OW[t], sa[t] landed

            // ---- GEMM1: cacc = h @ W^T  (single product) ----
            float cacc[16][4];
#pragma unroll
            for (int i = 0; i < 16; i++)
#pragma unroll
                for (int j = 0; j < 4; j++) cacc[i][j] = 0.0f;
            gemm1(smb + SM_HHI, smb + SM_W, cacc, R, lid);

            // ---- ei/ej partials from fp32 fragments + quad reduce ----
            float ei0 = 0.f, ej0 = 0.f, ei1 = 0.f, ej1 = 0.f;
            {
                const float* sav = sa + buf * 256;
#pragma unroll
                for (int q = 0; q < 16; q++) {
                    float s0 = sav[q * 8 + tg * 2], s1 = sav[q * 8 + tg * 2 + 1];
                    float d0 = sav[128 + q * 8 + tg * 2], d1 = sav[128 + q * 8 + tg * 2 + 1];
                    ei0 += cacc[q][0] * s0 + cacc[q][1] * s1;
                    ej0 += cacc[q][0] * d0 + cacc[q][1] * d1;
                    ei1 += cacc[q][2] * s0 + cacc[q][3] * s1;
                    ej1 += cacc[q][2] * d0 + cacc[q][3] * d1;
                }
#pragma unroll
                for (int o = 1; o < 4; o <<= 1) {
                    ei0 += __shfl_xor_sync(0xffffffffu, ei0, o);
                    ej0 += __shfl_xor_sync(0xffffffffu, ej0, o);
                    ei1 += __shfl_xor_sync(0xffffffffu, ei1, o);
                    ej1 += __shfl_xor_sync(0xffffffffu, ej1, o);
                }
            }

            // ---- pack Whh fragments to half2 (GEMM2/hp fp16 quantization) ----
            uint32_t pc01[16], pc23[16];
#pragma unroll
            for (int q = 0; q < 16; q++) {
                pc01[q] = pack2(cacc[q][0], cacc[q][1]);
                pc23[q] = pack2(cacc[q][2], cacc[q][3]);
            }

            // ---- warp-local softmax (rows r0=R+group batch0, r1=r0+8 batch1) ----
            float att0[8], att1[8];
            {
                float mx0 = -1e30f, mx1 = -1e30f;
#pragma unroll
                for (int m = 0; m < 8; m++) {
                    float ejm0 = __shfl_sync(0xffffffffu, ej0, m * 4 + tg);
                    float ejm1 = __shfl_sync(0xffffffffu, ej1, m * 4 + tg);
                    float w = ewf[group * 8 + m];
                    int   ad = adji[group * 8 + m];
                    float v0 = 0.f, v1 = 0.f;
                    if (ad) {
                        float x0 = ei0 + ejm0; v0 = (x0 > 0.f ? x0 : 0.2f * x0) * w;
                        float x1 = ei1 + ejm1; v1 = (x1 > 0.f ? x1 : 0.2f * x1) * w;
                    }
                    att0[m] = v0; att1[m] = v1;
                    mx0 = fmaxf(mx0, v0); mx1 = fmaxf(mx1, v1);
                }
                float s0 = 0.f, s1 = 0.f;
#pragma unroll
                for (int m = 0; m < 8; m++) {
                    att0[m] = __expf(att0[m] - mx0); s0 += att0[m];
                    att1[m] = __expf(att1[m] - mx1); s1 += att1[m];
                }
                float i0 = 1.f / s0, i1 = 1.f / s1;
#pragma unroll
                for (int m = 0; m < 8; m++) { att0[m] *= i0; att1[m] *= i1; }
            }

            // ---- hp = elu(att @ Whh) as 16 MMAs: batches stacked along k ----
            // A: rows 0-7 = batch0 (att0 at k0-7), rows 8-15 = batch1 (att1 at k8-15)
            // B per tile q: k0-7 = Whh_b0 node rows, k8-15 = Whh_b1; gathered from
            //   quad-packed pc01/pc23 via 4 shuffles + 2 byte-perms.
            uint32_t afHi[8][4];
            {
                uint32_t a_frag[4];
                a_frag[0] = pack2(att0[2 * tg], att0[2 * tg + 1]);   // r=g,   k lo
                a_frag[1] = 0u;                                      // r=g+8, k lo
                a_frag[2] = 0u;                                      // r=g,   k hi
                a_frag[3] = pack2(att1[2 * tg], att1[2 * tg + 1]);   // r=g+8, k hi
                const uint32_t sel = (group & 1) ? 0x7632u : 0x5410u;
                const int src0 = (2 * tg) * 4 + (group >> 1);
                const int src1 = src0 + 4;
#pragma unroll
                for (int q = 0; q < 16; q++) {
                    uint32_t w0 = __shfl_sync(0xffffffffu, pc01[q], src0);
                    uint32_t w1 = __shfl_sync(0xffffffffu, pc01[q], src1);
                    uint32_t v0 = __shfl_sync(0xffffffffu, pc23[q], src0);
                    uint32_t v1 = __shfl_sync(0xffffffffu, pc23[q], src1);
                    uint32_t b_frag[2];
                    b_frag[0] = __byte_perm(w0, w1, sel);   // batch0 rows 2tg,2tg+1
                    b_frag[1] = __byte_perm(v0, v1, sel);   // batch1 rows 2tg,2tg+1
                    float c4[4] = {0.f, 0.f, 0.f, 0.f};
                    mma16816(c4, a_frag, b_frag);
                    float h0a = c4[0], h0b = c4[1], h1a = c4[2], h1b = c4[3];
                    h0a = h0a > 0.f ? h0a : (__expf(h0a) - 1.f);
                    h0b = h0b > 0.f ? h0b : (__expf(h0b) - 1.f);
                    h1a = h1a > 0.f ? h1a : (__expf(h1a) - 1.f);
                    h1b = h1b > 0.f ? h1b : (__expf(h1b) - 1.f);
                    int kk = q >> 1, pos = (q & 1) << 1;
                    afHi[kk][pos]     = pack2(h0a, h0b);
                    afHi[kk][pos + 1] = pack2(h1a, h1b);
                }
            }

            // ---- GEMM2: gacc += hp @ outW^T (single product, A regs) ----
            {
                const int lm = lid >> 3, lr = lid & 7;
                const uint32_t boff = (uint32_t)(lr + ((lm >> 1) << 3)) * PB + ((lm & 1) << 4);
                const uint32_t bS = smb + SM_OW;
#pragma unroll
                for (int kk = 0; kk < 8; kk++) {
#pragma unroll
                    for (int jp = 0; jp < 8; jp++) {
                        uint32_t bh[4];
                        ldsm4(bh, bS + boff + (uint32_t)(jp * 16) * PB + kk * 32);
                        mma16816(gacc[2 * jp],     afHi[kk], bh);
                        mma16816(gacc[2 * jp + 1], afHi[kk], bh + 2);
                    }
                }
            }

            __syncthreads();   // all warps done with W, OW, sa[buf]
            if (t < 7) {       // prefetch next head (lands during LN / next GEMM1)
                stage_tile(smb + SM_W,  (const uint4*)(g_W  + ((t + 1) << 14)), tid);
                stage_tile(smb + SM_OW, (const uint4*)(g_OW + ((t + 1) << 14)), tid);
                if (tid < 64) cpa16(saA + (buf ^ 1) * 1024 + tid * 16,
                                    a_heads + (t + 1) * 256 + tid * 4);
                CP_COMMIT();
            }
        } // heads

        // ---- residual + bias + LayerNorm (warp-local rows; h = hi+lo) ----
        {
            const float* lb = lnb + l * 384;
            int r0 = R + group, r1 = r0 + 8;
            float s0 = 0.f, q0 = 0.f, s1 = 0.f, q1 = 0.f;
            float x0v[16][2], x1v[16][2];
#pragma unroll
            for (int jp = 0; jp < 16; jp++) {
                int col = jp * 8 + tg * 2;
                uint32_t h0h = *(uint32_t*)(sm + SM_HHI + r0 * PB + col * 2);
                uint32_t h0l = *(uint32_t*)(sm + SM_HLO + r0 * PB + col * 2);
                uint32_t h1h = *(uint32_t*)(sm + SM_HHI + r1 * PB + col * 2);
                uint32_t h1l = *(uint32_t*)(sm + SM_HLO + r1 * PB + col * 2);
                float x00 = gacc[jp][0] + hfu(h0h) + hfu(h0l) + lb[col];
                float x01 = gacc[jp][1] + hfu(h0h >> 16) + hfu(h0l >> 16) + lb[col + 1];
                float x10 = gacc[jp][2] + hfu(h1h) + hfu(h1l) + lb[col];
                float x11 = gacc[jp][3] + hfu(h1h >> 16) + hfu(h1l >> 16) + lb[col + 1];
                x0v[jp][0] = x00; x0v[jp][1] = x01;
                x1v[jp][0] = x10; x1v[jp][1] = x11;
                s0 += x00 + x01; q0 += x00 * x00 + x01 * x01;
                s1 += x10 + x11; q1 += x10 * x10 + x11 * x11;
            }
#pragma unroll
            for (int o = 1; o < 4; o <<= 1) {
                s0 += __shfl_xor_sync(0xffffffffu, s0, o);
                q0 += __shfl_xor_sync(0xffffffffu, q0, o);
                s1 += __shfl_xor_sync(0xffffffffu, s1, o);
                q1 += __shfl_xor_sync(0xffffffffu, q1, o);
            }
            float mu0 = s0 * 0.0078125f, mu1 = s1 * 0.0078125f;
            float rstd0 = rsqrtf(q0 * 0.0078125f - mu0 * mu0 + 1e-5f);
            float rstd1 = rsqrtf(q1 * 0.0078125f - mu1 * mu1 + 1e-5f);
#pragma unroll
            for (int jp = 0; jp < 16; jp++) {
                int col = jp * 8 + tg * 2;
                float y00 = (x0v[jp][0] - mu0) * rstd0 * lb[128 + col]     + lb[256 + col];
                float y01 = (x0v[jp][1] - mu0) * rstd0 * lb[128 + col + 1] + lb[256 + col + 1];
                float y10 = (x1v[jp][0] - mu1) * rstd1 * lb[128 + col]     + lb[256 + col];
                float y11 = (x1v[jp][1] - mu1) * rstd1 * lb[128 + col + 1] + lb[256 + col + 1];
                if (l == 0) {
                    uint32_t w0 = pack2(y00, y01), w1 = pack2(y10, y11);
                    *(uint32_t*)(sm + SM_HHI + r0 * PB + col * 2) = w0;
                    *(uint32_t*)(sm + SM_HLO + r0 * PB + col * 2) =
                        pack2lo(y00, hfu(w0), y01, hfu(w0 >> 16));
                    *(uint32_t*)(sm + SM_HHI + r1 * PB + col * 2) = w1;
                    *(uint32_t*)(sm + SM_HLO + r1 * PB + col * 2) =
                        pack2lo(y10, hfu(w1), y11, hfu(w1 >> 16));
                } else {
                    *(float2*)(out + ((long)blockIdx.x * 64 + r0) * 128 + col) =
                        make_float2(y00, y01);
                    *(float2*)(out + ((long)blockIdx.x * 64 + r1) * 128 + col) =
                        make_float2(y10, y11);
                }
            }
            __syncwarp();   // h-tile writes visible to next-layer GEMM1 (warp-local)
        }
    } // layers
}

// ---------------------------------------------------------------------------
extern "C" void kernel_launch(void* const* d_in, const int* in_sizes, int n_in,
                              void* d_out, int out_size)
{
    const float* se      = (const float*)d_in[0];
    const float* te      = (const float*)d_in[1];
    const float* W_in    = (const float*)d_in[2];
    const float* b_in    = (const float*)d_in[3];
    const float* W_heads = (const float*)d_in[4];
    const float* a_heads = (const float*)d_in[5];
    const float* out_W   = (const float*)d_in[6];
    const float* out_b   = (const float*)d_in[7];
    const float* ln_s    = (const float*)d_in[8];
    const float* ln_b    = (const float*)d_in[9];
    const float* om_i    = (const float*)d_in[10];
    const float* om_c    = (const float*)d_in[11];
    const int*   adj     = (const int*)d_in[12];
    const int*   et      = (const int*)d_in[13];
    float* out = (float*)d_out;

    int B = in_sizes[0] / 128;
    size_t tail = (size_t)B * 8 * 128;

    prep<<<512, 256>>>(te, W_in, b_in, W_heads, out_W, om_i, om_c, adj, et, out + tail);

    cudaFuncSetAttribute(gat_tc, cudaFuncAttributeMaxDynamicSharedMemorySize, SMEM_BYTES);
    gat_tc<<<B / 8, 128, SMEM_BYTES>>>(se, a_heads, out_b, ln_s, ln_b,
                                       adj, et, om_i, om_c, out);
}

// round 14
// speedup vs baseline: 2.1171x; 1.0017x over previous
#include <cuda_runtime.h>
#include <cuda_fp16.h>
#include <cstdint>
#include <math.h>

// ===========================================================================
// TaskGraphGAT — round 13: ei/ej folded into GEMM1 as two extra B-rows
// (wa = W^T a precomputed in prep), prefetch split W/OW with wait_group 1
// for real compute/copy overlap. Rest identical to R13 best (425us).
// ===========================================================================

#define PB 272          // fp16 tile pitch in BYTES (136 halves)

// ---------------- SMEM map (bytes) ----------------
#define SM_HHI   0          // h hi (64 x 136 fp16 = 17408 B) -> GEMM1 A
#define SM_HLO   17408      // h lo (residual accuracy only)
#define SM_W     34816      // W tile fp16, 136 rows x PB = 36992 B (rows 128/129 = wa)
#define SM_OW    71808      // outW tile fp16, 128 rows x PB = 34816 B
#define SM_SMALL 106624     // lnb[768] | ewf[64] | adji[64]
#define SMEM_BYTES 110208

// ---------------- device globals (written by prep) ----------------
__device__ float g_htask[8 * 128];
__device__ __align__(16) __half g_W[8 * 18496];    // pre-pitched 136x136 tiles
__device__ __align__(16) __half g_OW[8 * 16384];   // out_W rearranged fp16

// ---------------- helpers ----------------
__device__ __forceinline__ uint32_t smem_u32(const void* p) {
    uint32_t a;
    asm("{ .reg .u64 t; cvta.to.shared.u64 t, %1; cvt.u32.u64 %0, t; }" : "=r"(a) : "l"(p));
    return a;
}
__device__ __forceinline__ void ldsm4(uint32_t* r, uint32_t a) {
    asm volatile("ldmatrix.sync.aligned.m8n8.x4.shared.b16 {%0,%1,%2,%3}, [%4];"
                 : "=r"(r[0]), "=r"(r[1]), "=r"(r[2]), "=r"(r[3]) : "r"(a));
}
__device__ __forceinline__ void ldsm2(uint32_t* r, uint32_t a) {
    asm volatile("ldmatrix.sync.aligned.m8n8.x2.shared.b16 {%0,%1}, [%2];"
                 : "=r"(r[0]), "=r"(r[1]) : "r"(a));
}
__device__ __forceinline__ void mma16816(float* c, const uint32_t* a, const uint32_t* b) {
    asm volatile(
        "mma.sync.aligned.m16n8k16.row.col.f32.f16.f16.f32 "
        "{%0,%1,%2,%3}, {%4,%5,%6,%7}, {%8,%9}, {%0,%1,%2,%3};"
        : "+f"(c[0]), "+f"(c[1]), "+f"(c[2]), "+f"(c[3])
        : "r"(a[0]), "r"(a[1]), "r"(a[2]), "r"(a[3]), "r"(b[0]), "r"(b[1]));
}
__device__ __forceinline__ void cpa16(uint32_t dst, const void* src) {
    asm volatile("cp.async.cg.shared.global [%0], [%1], 16;" :: "r"(dst), "l"(src));
}
#define CP_COMMIT() asm volatile("cp.async.commit_group;" ::: "memory")
#define CP_WAIT0()  asm volatile("cp.async.wait_group 0;" ::: "memory")
#define CP_WAIT1()  asm volatile("cp.async.wait_group 1;" ::: "memory")

__device__ __forceinline__ uint32_t pack2(float x0, float x1) {
    __half2 v = __floats2half2_rn(x0, x1);
    return *(uint32_t*)&v;
}
__device__ __forceinline__ float hfu(uint32_t u) {
    return __half2float(__ushort_as_half((unsigned short)(u & 0xffff)));
}
__device__ __forceinline__ uint32_t pack2lo(float x0, float h0, float x1, float h1) {
    __half2 v = __floats2half2_rn(x0 - h0, x1 - h1);
    return *(uint32_t*)&v;
}

// stage OW (dense 128x128 -> pitched) via cp.async (128 thr)
__device__ __forceinline__ void stage_tile(uint32_t dst, const uint4* src, int tid) {
#pragma unroll
    for (int i = tid; i < 2048; i += 128) {
        uint32_t d = ((uint32_t)(i >> 4) * PB) + ((i & 15) << 4);
        cpa16(dst + d, src + i);
    }
}
// stage W (pre-pitched 136xPB tile -> linear copy, 2312 uint4)
__device__ __forceinline__ void stage_w(uint32_t dst, const uint4* src, int tid) {
#pragma unroll
    for (int i = tid; i < 2312; i += 128) cpa16(dst + (uint32_t)i * 16, src + i);
}

// GEMM1: c[q][0..3] += A[rows R..R+15] @ W^T; cE += ei/ej cols (B rows 128/129)
__device__ __forceinline__ void gemm1(uint32_t aHi, uint32_t bW,
                                      float (&c)[16][4], float (&cE)[4],
                                      int R, int lid) {
    const int lm = lid >> 3, lr = lid & 7;
    const uint32_t aoff = (uint32_t)(R + lr + ((lm & 1) << 3)) * PB + ((lm >> 1) << 4);
    const uint32_t boff = (uint32_t)(lr + ((lm >> 1) << 3)) * PB + ((lm & 1) << 4);
    const uint32_t eoff = (uint32_t)(128 + (lid & 7)) * PB + (((lid >> 3) & 1) << 4);
#pragma unroll 2
    for (int k = 0; k < 8; k++) {
        uint32_t ah[4];
        ldsm4(ah, aHi + aoff + k * 32);
        uint32_t bE[2];
        ldsm2(bE, bW + eoff + k * 32);
        mma16816(cE, ah, bE);
#pragma unroll
        for (int jp = 0; jp < 8; jp++) {
            uint32_t bh[4];
            ldsm4(bh, bW + boff + (uint32_t)(jp * 16) * PB + k * 32);
            mma16816(c[2 * jp],     ah, bh);
            mma16816(c[2 * jp + 1], ah, bh + 2);
        }
    }
}

// ---------------- single setup kernel ----------------
__global__ void prep(const float* __restrict__ te, const float* __restrict__ W_in,
                     const float* __restrict__ b_in, const float* __restrict__ Wh,
                     const float* __restrict__ OW, const float* __restrict__ ah,
                     const float* __restrict__ om_i, const float* __restrict__ om_c,
                     const int* __restrict__ adj, const int* __restrict__ et,
                     float* __restrict__ out_tail) {
    int idx = blockIdx.x * 256 + threadIdx.x;   // grid 512 -> 131072 = 8*16384
    {
        int t = idx >> 14, rem = idx & 16383, row = rem >> 7, col = rem & 127;
        g_W[t * 18496 + row * 136 + col] = __float2half(Wh[idx]);
        int l = t >> 2, hh = t & 3;              // out_W[l][c=row][hh*128+g=col]
        g_OW[idx] = __float2half(OW[l * 65536 + row * 512 + hh * 128 + col]);
    }
    // wa rows (ei/ej fold): blocks 504..511 handle tile t = blockIdx.x - 504
    if (blockIdx.x >= 504) {
        int t = blockIdx.x - 504;
        int f = threadIdx.x;
        if (f < 128) {
            const float* wt = Wh + t * 16384;
            const float* av = ah + t * 256;
            float ss = 0.f, sd = 0.f;
#pragma unroll 4
            for (int g = 0; g < 128; g++) {
                float w = wt[g * 128 + f];
                ss += w * av[g];
                sd += w * av[128 + g];
            }
            __half* tw = g_W + t * 18496;
            tw[128 * 136 + f] = __float2half(ss);
            tw[129 * 136 + f] = __float2half(sd);
#pragma unroll
            for (int r = 130; r < 136; r++) tw[r * 136 + f] = __float2half(0.f);
        }
    }
    if (blockIdx.x == 0) {
        int t = threadIdx.x;
        if (t < 64) {
            float w = 0.f;
            if (adj[t]) { int e = et[t]; w = (e == 1) ? om_i[0] : ((e == 2) ? om_c[0] : 1.f); }
            out_tail[t] = w;
        }
        for (int i2 = t; i2 < 1024; i2 += 256) {
            int n = i2 >> 7, o = i2 & 127;
            const float* tr = te + n * 64;
            const float* wr = W_in + o * 64;
            float s = b_in[o];
#pragma unroll 8
            for (int d = 0; d < 64; d++) s += tr[d] * wr[d];
            g_htask[i2] = s;
        }
    }
}

// ---------------- main kernel ----------------
__global__ __launch_bounds__(128, 2)
void gat_tc(const float* __restrict__ se,
            const float* __restrict__ out_b, const float* __restrict__ ln_s,
            const float* __restrict__ ln_b, const int* __restrict__ adj,
            const int* __restrict__ et, const float* __restrict__ om_i,
            const float* __restrict__ om_c, float* __restrict__ out)
{
    extern __shared__ __align__(1024) unsigned char sm[];
    float* smf  = (float*)(sm + SM_SMALL);
    float* lnb  = smf;                // [2][384]: out_b | ln_scale | ln_bias
    float* ewf  = smf + 768;          // [64]
    int*   adji = (int*)(smf + 832);  // [64]

    const uint32_t smb = smem_u32(sm);
    const int tid = threadIdx.x;
    const int lid = tid & 31;
    const int wid = tid >> 5;                 // 0..3
    const int R     = wid << 4;               // warp's 16 rows
    const int group = lid >> 2;
    const int tg    = lid & 3;
    const long b0 = (long)blockIdx.x * 8;     // 8 batch elems per CTA

    // ---- prefetch head-0 W (group0) then OW (group1) ----
    stage_w(smb + SM_W, (const uint4*)g_W, tid);
    CP_COMMIT();
    stage_tile(smb + SM_OW, (const uint4*)g_OW, tid);
    CP_COMMIT();

    // ---- small constants ----
    if (tid < 64) {
        int e = et[tid];
        ewf[tid] = adj[tid] ? ((e == 1) ? om_i[0] : ((e == 2) ? om_c[0] : 1.f)) : 0.f;
        adji[tid] = adj[tid];
    }
#pragma unroll
    for (int l = 0; l < 2; l++) {
        lnb[l * 384 + tid]       = out_b[l * 128 + tid];
        lnb[l * 384 + 128 + tid] = ln_s[l * 128 + tid];
        lnb[l * 384 + 256 + tid] = ln_b[l * 128 + tid];
    }

    // ---- build h tiles (hi used by GEMM1; lo only for residual): 64 rows ----
    {
        int r = tid & 63, f0 = (tid >> 6) * 64;
        const float* ser = se + (b0 + (r >> 3)) * 128;
        const float* htr = g_htask + (r & 7) * 128;
#pragma unroll 8
        for (int j = 0; j < 64; j += 2) {
            int f = f0 + j;
            float x0 = ser[f] + htr[f];
            float x1 = ser[f + 1] + htr[f + 1];
            uint32_t hiw = pack2(x0, x1);
            *(uint32_t*)(sm + SM_HHI + r * PB + f * 2) = hiw;
            *(uint32_t*)(sm + SM_HLO + r * PB + f * 2) =
                pack2lo(x0, hfu(hiw), x1, hfu(hiw >> 16));
        }
    }

    for (int l = 0; l < 2; l++) {
        float gacc[16][4];
#pragma unroll
        for (int i = 0; i < 16; i++)
#pragma unroll
            for (int j = 0; j < 4; j++) gacc[i][j] = 0.0f;

        for (int hh = 0; hh < 4; hh++) {
            const int t = l * 4 + hh;

            CP_WAIT1();          // W[t] landed (OW[t] may still be in flight)
            __syncthreads();

            // ---- GEMM1: cacc = h @ W^T ; cE = [ei0, ej0, ei1, ej1] fold ----
            float cacc[16][4], cE[4];
#pragma unroll
            for (int i = 0; i < 16; i++)
#pragma unroll
                for (int j = 0; j < 4; j++) cacc[i][j] = 0.0f;
            cE[0] = cE[1] = cE[2] = cE[3] = 0.0f;
            gemm1(smb + SM_HHI, smb + SM_W, cacc, cE, R, lid);

            __syncthreads();     // W[t] readers done -> safe to overwrite
            if (t < 7) {         // prefetch W[t+1]: overlaps softmax/hp/GEMM2
                stage_w(smb + SM_W, (const uint4*)(g_W + (size_t)(t + 1) * 18496), tid);
                CP_COMMIT();
            }

            // ---- pack Whh fragments to half2 (hp/GEMM2 fp16 quantization) ----
            uint32_t pc01[16], pc23[16];
#pragma unroll
            for (int q = 0; q < 16; q++) {
                pc01[q] = pack2(cacc[q][0], cacc[q][1]);
                pc23[q] = pack2(cacc[q][2], cacc[q][3]);
            }

            // ---- warp-local softmax; ei/ej live in cE at tg=0 lanes ----
            float att0[8], att1[8];
            {
                float ei0 = __shfl_sync(0xffffffffu, cE[0], group * 4);
                float ei1 = __shfl_sync(0xffffffffu, cE[2], group * 4);
                float mx0 = -1e30f, mx1 = -1e30f;
#pragma unroll
                for (int m = 0; m < 8; m++) {
                    float ejm0 = __shfl_sync(0xffffffffu, cE[1], m * 4);
                    float ejm1 = __shfl_sync(0xffffffffu, cE[3], m * 4);
                    float w = ewf[group * 8 + m];
                    int   ad = adji[group * 8 + m];
                    float v0 = 0.f, v1 = 0.f;
                    if (ad) {
                        float x0 = ei0 + ejm0; v0 = (x0 > 0.f ? x0 : 0.2f * x0) * w;
                        float x1 = ei1 + ejm1; v1 = (x1 > 0.f ? x1 : 0.2f * x1) * w;
                    }
                    att0[m] = v0; att1[m] = v1;
                    mx0 = fmaxf(mx0, v0); mx1 = fmaxf(mx1, v1);
                }
                float s0 = 0.f, s1 = 0.f;
#pragma unroll
                for (int m = 0; m < 8; m++) {
                    att0[m] = __expf(att0[m] - mx0); s0 += att0[m];
                    att1[m] = __expf(att1[m] - mx1); s1 += att1[m];
                }
                float i0 = 1.f / s0, i1 = 1.f / s1;
#pragma unroll
                for (int m = 0; m < 8; m++) { att0[m] *= i0; att1[m] *= i1; }
            }

            // ---- hp = elu(att @ Whh) as 16 MMAs: batches stacked along k ----
            uint32_t afHi[8][4];
            {
                uint32_t a_frag[4];
                a_frag[0] = pack2(att0[2 * tg], att0[2 * tg + 1]);   // r=g,   k lo
                a_frag[1] = 0u;
                a_frag[2] = 0u;
                a_frag[3] = pack2(att1[2 * tg], att1[2 * tg + 1]);   // r=g+8, k hi
                const uint32_t sel = (group & 1) ? 0x7632u : 0x5410u;
                const int src0 = (2 * tg) * 4 + (group >> 1);
                const int src1 = src0 + 4;
#pragma unroll
                for (int q = 0; q < 16; q++) {
                    uint32_t w0 = __shfl_sync(0xffffffffu, pc01[q], src0);
                    uint32_t w1 = __shfl_sync(0xffffffffu, pc01[q], src1);
                    uint32_t v0 = __shfl_sync(0xffffffffu, pc23[q], src0);
                    uint32_t v1 = __shfl_sync(0xffffffffu, pc23[q], src1);
                    uint32_t b_frag[2];
                    b_frag[0] = __byte_perm(w0, w1, sel);   // batch0 rows 2tg,2tg+1
                    b_frag[1] = __byte_perm(v0, v1, sel);   // batch1 rows 2tg,2tg+1
                    float c4[4] = {0.f, 0.f, 0.f, 0.f};
                    mma16816(c4, a_frag, b_frag);
                    float h0a = c4[0], h0b = c4[1], h1a = c4[2], h1b = c4[3];
                    h0a = h0a > 0.f ? h0a : (__expf(h0a) - 1.f);
                    h0b = h0b > 0.f ? h0b : (__expf(h0b) - 1.f);
                    h1a = h1a > 0.f ? h1a : (__expf(h1a) - 1.f);
                    h1b = h1b > 0.f ? h1b : (__expf(h1b) - 1.f);
                    int kk = q >> 1, pos = (q & 1) << 1;
                    afHi[kk][pos]     = pack2(h0a, h0b);
                    afHi[kk][pos + 1] = pack2(h1a, h1b);
                }
            }

            if (t < 7) CP_WAIT1(); else CP_WAIT0();   // OW[t] landed
            __syncthreads();

            // ---- GEMM2: gacc += hp @ outW^T (single product, A regs) ----
            {
                const int lm = lid >> 3, lr = lid & 7;
                const uint32_t boff = (uint32_t)(lr + ((lm >> 1) << 3)) * PB + ((lm & 1) << 4);
                const uint32_t bS = smb + SM_OW;
#pragma unroll
                for (int kk = 0; kk < 8; kk++) {
#pragma unroll
                    for (int jp = 0; jp < 8; jp++) {
                        uint32_t bh[4];
                        ldsm4(bh, bS + boff + (uint32_t)(jp * 16) * PB + kk * 32);
                        mma16816(gacc[2 * jp],     afHi[kk], bh);
                        mma16816(gacc[2 * jp + 1], afHi[kk], bh + 2);
                    }
                }
            }

            __syncthreads();     // OW[t] readers done -> safe to overwrite
            if (t < 7) {         // prefetch OW[t+1]: overlaps next head's GEMM1..hp
                stage_tile(smb + SM_OW, (const uint4*)(g_OW + ((t + 1) << 14)), tid);
                CP_COMMIT();
            }
        } // heads

        // ---- residual + bias + LayerNorm (warp-local rows; h = hi+lo) ----
        {
            const float* lb = lnb + l * 384;
            int r0 = R + group, r1 = r0 + 8;
            float s0 = 0.f, q0 = 0.f, s1 = 0.f, q1 = 0.f;
            float x0v[16][2], x1v[16][2];
#pragma unroll
            for (int jp = 0; jp < 16; jp++) {
                int col = jp * 8 + tg * 2;
                uint32_t h0h = *(uint32_t*)(sm + SM_HHI + r0 * PB + col * 2);
                uint32_t h0l = *(uint32_t*)(sm + SM_HLO + r0 * PB + col * 2);
                uint32_t h1h = *(uint32_t*)(sm + SM_HHI + r1 * PB + col * 2);
                uint32_t h1l = *(uint32_t*)(sm + SM_HLO + r1 * PB + col * 2);
                float x00 = gacc[jp][0] + hfu(h0h) + hfu(h0l) + lb[col];
                float x01 = gacc[jp][1] + hfu(h0h >> 16) + hfu(h0l >> 16) + lb[col + 1];
                float x10 = gacc[jp][2] + hfu(h1h) + hfu(h1l) + lb[col];
                float x11 = gacc[jp][3] + hfu(h1h >> 16) + hfu(h1l >> 16) + lb[col + 1];
                x0v[jp][0] = x00; x0v[jp][1] = x01;
                x1v[jp][0] = x10; x1v[jp][1] = x11;
                s0 += x00 + x01; q0 += x00 * x00 + x01 * x01;
                s1 += x10 + x11; q1 += x10 * x10 + x11 * x11;
            }
#pragma unroll
            for (int o = 1; o < 4; o <<= 1) {
                s0 += __shfl_xor_sync(0xffffffffu, s0, o);
                q0 += __shfl_xor_sync(0xffffffffu, q0, o);
                s1 += __shfl_xor_sync(0xffffffffu, s1, o);
                q1 += __shfl_xor_sync(0xffffffffu, q1, o);
            }
            float mu0 = s0 * 0.0078125f, mu1 = s1 * 0.0078125f;
            float rstd0 = rsqrtf(q0 * 0.0078125f - mu0 * mu0 + 1e-5f);
            float rstd1 = rsqrtf(q1 * 0.0078125f - mu1 * mu1 + 1e-5f);
#pragma unroll
            for (int jp = 0; jp < 16; jp++) {
                int col = jp * 8 + tg * 2;
                float y00 = (x0v[jp][0] - mu0) * rstd0 * lb[128 + col]     + lb[256 + col];
                float y01 = (x0v[jp][1] - mu0) * rstd0 * lb[128 + col + 1] + lb[256 + col + 1];
                float y10 = (x1v[jp][0] - mu1) * rstd1 * lb[128 + col]     + lb[256 + col];
                float y11 = (x1v[jp][1] - mu1) * rstd1 * lb[128 + col + 1] + lb[256 + col + 1];
                if (l == 0) {
                    uint32_t w0 = pack2(y00, y01), w1 = pack2(y10, y11);
                    *(uint32_t*)(sm + SM_HHI + r0 * PB + col * 2) = w0;
                    *(uint32_t*)(sm + SM_HLO + r0 * PB + col * 2) =
                        pack2lo(y00, hfu(w0), y01, hfu(w0 >> 16));
                    *(uint32_t*)(sm + SM_HHI + r1 * PB + col * 2) = w1;
                    *(uint32_t*)(sm + SM_HLO + r1 * PB + col * 2) =
                        pack2lo(y10, hfu(w1), y11, hfu(w1 >> 16));
                } else {
                    *(float2*)(out + ((long)blockIdx.x * 64 + r0) * 128 + col) =
                        make_float2(y00, y01);
                    *(float2*)(out + ((long)blockIdx.x * 64 + r1) * 128 + col) =
                        make_float2(y10, y11);
                }
            }
            __syncwarp();   // h-tile writes visible to next-layer GEMM1 (warp-local)
        }
    } // layers
}

// ---------------------------------------------------------------------------
extern "C" void kernel_launch(void* const* d_in, const int* in_sizes, int n_in,
                              void* d_out, int out_size)
{
    const float* se      = (const float*)d_in[0];
    const float* te      = (const float*)d_in[1];
    const float* W_in    = (const float*)d_in[2];
    const float* b_in    = (const float*)d_in[3];
    const float* W_heads = (const float*)d_in[4];
    const float* a_heads = (const float*)d_in[5];
    const float* out_W   = (const float*)d_in[6];
    const float* out_b   = (const float*)d_in[7];
    const float* ln_s    = (const float*)d_in[8];
    const float* ln_b    = (const float*)d_in[9];
    const float* om_i    = (const float*)d_in[10];
    const float* om_c    = (const float*)d_in[11];
    const int*   adj     = (const int*)d_in[12];
    const int*   et      = (const int*)d_in[13];
    float* out = (float*)d_out;

    int B = in_sizes[0] / 128;
    size_t tail = (size_t)B * 8 * 128;

    prep<<<512, 256>>>(te, W_in, b_in, W_heads, out_W, a_heads,
                       om_i, om_c, adj, et, out + tail);

    cudaFuncSetAttribute(gat_tc, cudaFuncAttributeMaxDynamicSharedMemorySize, SMEM_BYTES);
    gat_tc<<<B / 8, 128, SMEM_BYTES>>>(se, out_b, ln_s, ln_b,
                                       adj, et, om_i, om_c, out);
}